// round 13
// baseline (speedup 1.0000x reference)
#include <cuda_runtime.h>
#include <cuda_bf16.h>
#include <cstdint>
#include <math.h>

// ---------------- problem constants ----------------
#define CB   4
#define CS   512
#define CD   2048
#define CNH  8
#define CDEG 4
#define CHD  256
#define CAH  16
#define CAHD 128
#define CDQ  512
#define CNC  (CNH*CDEG*CHD)   // 8192
#define MT   (CB*CS)          // 2048 tokens

// ---------------- fp32 scratch ----------------
__device__ float g_xn   [MT*CD];
__device__ float g_xmean[CB*CD];
__device__ float g_hs   [CB*CDQ];
__device__ float g_coef [CB*CNC];
__device__ float g_v    [MT*CD];
__device__ float g_sc   [(size_t)CB*CAH*CS*CS];
__device__ float g_slr  [MT*CD];
__device__ float g_gv   [MT*2*CD];
__device__ float g_cw1  [(size_t)8*128*(2*CD)];

// ---------------- bf16 split scratch (3x K) ----------------
__device__ __align__(16) __nv_bfloat16 g3_xn   [MT*3*CD];
__device__ __align__(16) __nv_bfloat16 g3_kv   [MT*3*CD];
__device__ __align__(16) __nv_bfloat16 g3_attn [MT*3*CD];
__device__ __align__(16) __nv_bfloat16 g3_fus  [MT*3*CD];
__device__ __align__(16) __nv_bfloat16 g3_h2   [(size_t)MT*3*CD];
__device__ __align__(16) __nv_bfloat16 g3_q    [MT*3*CD];
__device__ __align__(16) __nv_bfloat16 g3_k    [MT*3*CD];
__device__ __align__(16) __nv_bfloat16 g3_p    [(size_t)CB*CAH*CS*3*CS];
__device__ __align__(16) __nv_bfloat16 g3_vt   [(size_t)CB*CAH*CAHD*3*CS];
__device__ __align__(16) __nv_bfloat16 g3_wq   [(size_t)CD*3*CD];
__device__ __align__(16) __nv_bfloat16 g3_wk   [(size_t)CD*3*CD];
__device__ __align__(16) __nv_bfloat16 g3_wv   [(size_t)CD*3*CD];
__device__ __align__(16) __nv_bfloat16 g3_wo   [(size_t)CD*3*CD];
__device__ __align__(16) __nv_bfloat16 g3_wout [(size_t)CD*3*CD];
__device__ __align__(16) __nv_bfloat16 g3_wfgvb[(size_t)(2*CD)*3*CD];
__device__ __align__(16) __nv_bfloat16 g3_wt1  [(size_t)8*(2*CD)*768];
__device__ __align__(16) __nv_bfloat16 g3_cf   [(size_t)8*128*768];
__device__ __align__(16) __nv_bfloat16 g3_cw1t [(size_t)CB*(2*CD)*96];
__device__ __align__(16) __nv_bfloat16 g3_tsc  [(size_t)MT*96];

// ---------------- helpers ----------------
__device__ __forceinline__ uint32_t smem_u32(const void* p) {
    uint32_t a;
    asm("{ .reg .u64 t; cvta.to.shared.u64 t, %1; cvt.u32.u64 %0, t; }" : "=r"(a) : "l"(p));
    return a;
}
__device__ __forceinline__ void cp16(uint32_t dst, const void* src) {
    asm volatile("cp.async.cg.shared.global [%0], [%1], 16;" :: "r"(dst), "l"(src) : "memory");
}
__device__ __forceinline__ void cp_commit() { asm volatile("cp.async.commit_group;" ::: "memory"); }

__device__ __forceinline__ void ldm_x4(uint32_t addr, uint32_t& r0, uint32_t& r1,
                                       uint32_t& r2, uint32_t& r3) {
    asm volatile("ldmatrix.sync.aligned.m8n8.x4.shared.b16 {%0,%1,%2,%3}, [%4];"
                 : "=r"(r0), "=r"(r1), "=r"(r2), "=r"(r3) : "r"(addr));
}
__device__ __forceinline__ void mma16816(float* c, const uint32_t* a, const uint32_t* b) {
    asm volatile("mma.sync.aligned.m16n8k16.row.col.f32.bf16.bf16.f32 "
                 "{%0,%1,%2,%3}, {%4,%5,%6,%7}, {%8,%9}, {%0,%1,%2,%3};"
                 : "+f"(c[0]), "+f"(c[1]), "+f"(c[2]), "+f"(c[3])
                 : "r"(a[0]), "r"(a[1]), "r"(a[2]), "r"(a[3]), "r"(b[0]), "r"(b[1]));
}

__device__ __forceinline__ void split2(float a, __nv_bfloat16& hi, __nv_bfloat16& lo) {
    hi = __float2bfloat16(a);
    lo = __float2bfloat16(a - __bfloat162float(hi));
}

// ---------------- reductions (blockDim == 256) ----------------
__device__ __forceinline__ float warpSum(float v) {
    #pragma unroll
    for (int o = 16; o > 0; o >>= 1) v += __shfl_xor_sync(0xffffffffu, v, o);
    return v;
}
__device__ __forceinline__ float warpMax(float v) {
    #pragma unroll
    for (int o = 16; o > 0; o >>= 1) v = fmaxf(v, __shfl_xor_sync(0xffffffffu, v, o));
    return v;
}
__device__ __forceinline__ float blockSum(float v) {
    __shared__ float sh[8];
    v = warpSum(v);
    __syncthreads();
    if ((threadIdx.x & 31) == 0) sh[threadIdx.x >> 5] = v;
    __syncthreads();
    float r = sh[0];
    #pragma unroll
    for (int i = 1; i < 8; i++) r += sh[i];
    return r;
}
__device__ __forceinline__ float blockMax(float v) {
    __shared__ float shm[8];
    v = warpMax(v);
    __syncthreads();
    if ((threadIdx.x & 31) == 0) shm[threadIdx.x >> 5] = v;
    __syncthreads();
    float r = shm[0];
    #pragma unroll
    for (int i = 1; i < 8; i++) r = fmaxf(r, shm[i]);
    return r;
}

// =================== persistent HMMA bf16 GEMM (R6, FROZEN) ================
#define ROWB 80
#define TILEB (128*ROWB)
#define STGB  (2*TILEB)
#define NSTG  4
#define MM_SMEM (NSTG*STGB)  // 81920

struct MMParams {
    const __nv_bfloat16* A;
    const __nv_bfloat16* B;
    float* C;
    const float* Add;
    __nv_bfloat16* S3;
    int lda, ldb, ldc, K3;
    float alpha;
    int bdiv;
    long long sAo, sAi, sBo, sBi, sCo, sCi;
    int tilesM, tilesN, total;
    int mode;        // 0 fp32 C(+Add); 1 q3 split; 2 k3 split; 3 attn3 split
    int causal;
};

__global__ void __launch_bounds__(256, 2)
mm_bf16_kernel(MMParams p) {
    extern __shared__ __align__(128) char sm[];

    const int tid  = threadIdx.x, lane = tid & 31, wid = tid >> 5;
    const int wm   = wid >> 2, wn = wid & 3;
    const uint32_t sbase = smem_u32(sm);
    const int lrow = tid >> 1;
    const int lch  = (tid & 1) * 2;
    const uint32_t sAw = sbase + lrow * ROWB + lch * 16;
    const uint32_t sBw = sAw + TILEB;
    const int lr15 = lane & 15, lhi = lane >> 4;
    const uint32_t aoff = (uint32_t)((wm * 64 + lr15) * ROWB + lhi * 16);
    const uint32_t boff = (uint32_t)((wn * 32 + lr15) * ROWB + lhi * 16) + TILEB;
    const int tilesMN = p.tilesM * p.tilesN;
    const int NK = p.K3 / 32;

    for (int t = blockIdx.x; t < p.total; t += gridDim.x) {
        int z  = t / tilesMN;
        int r  = t - z * tilesMN;
        int ty = r / p.tilesN, tx = r - ty * p.tilesN;
        if (p.causal && tx > ty) continue;
        int zo = z / p.bdiv, zi = z - zo * p.bdiv;

        const __nv_bfloat16* Agb = p.A + zo * p.sAo + zi * p.sAi
                                   + (long long)(ty * 128 + lrow) * p.lda + lch * 8;
        const __nv_bfloat16* Bgb = p.B + zo * p.sBo + zi * p.sBi
                                   + (long long)(tx * 128 + lrow) * p.ldb + lch * 8;

        float acc[4][4][4];
        #pragma unroll
        for (int i = 0; i < 4; i++)
            #pragma unroll
            for (int j = 0; j < 4; j++)
                #pragma unroll
                for (int e = 0; e < 4; e++) acc[i][j][e] = 0.f;

        #pragma unroll
        for (int s = 0; s < 3; s++) {
            uint32_t o = (uint32_t)s * STGB;
            const __nv_bfloat16* Ag = Agb + s * 32;
            const __nv_bfloat16* Bg = Bgb + s * 32;
            cp16(sAw + o,      Ag);
            cp16(sAw + o + 16, Ag + 8);
            cp16(sBw + o,      Bg);
            cp16(sBw + o + 16, Bg + 8);
            cp_commit();
        }

        for (int kc = 0; kc < NK; kc++) {
            asm volatile("cp.async.wait_group 2;" ::: "memory");
            __syncthreads();
            if (kc + 3 < NK) {
                uint32_t o = (uint32_t)((kc + 3) & 3) * STGB;
                const __nv_bfloat16* Ag = Agb + (kc + 3) * 32;
                const __nv_bfloat16* Bg = Bgb + (kc + 3) * 32;
                cp16(sAw + o,      Ag);
                cp16(sAw + o + 16, Ag + 8);
                cp16(sBw + o,      Bg);
                cp16(sBw + o + 16, Bg + 8);
            }
            cp_commit();

            uint32_t sA = sbase + (uint32_t)(kc & 3) * STGB + aoff;
            uint32_t sB = sbase + (uint32_t)(kc & 3) * STGB + boff;
            #pragma unroll
            for (int ks = 0; ks < 2; ks++) {
                uint32_t a[4][4];
                #pragma unroll
                for (int mt = 0; mt < 4; mt++)
                    ldm_x4(sA + mt * (16 * ROWB) + ks * 32, a[mt][0], a[mt][1], a[mt][2], a[mt][3]);
                uint32_t b[4][2];
                #pragma unroll
                for (int bt = 0; bt < 2; bt++) {
                    uint32_t r0, r1, r2, r3;
                    ldm_x4(sB + bt * (16 * ROWB) + ks * 32, r0, r1, r2, r3);
                    b[bt * 2 + 0][0] = r0; b[bt * 2 + 0][1] = r2;
                    b[bt * 2 + 1][0] = r1; b[bt * 2 + 1][1] = r3;
                }
                #pragma unroll
                for (int mt = 0; mt < 4; mt++)
                    #pragma unroll
                    for (int nt = 0; nt < 4; nt++)
                        mma16816(acc[mt][nt], a[mt], b[nt]);
            }
        }
        __syncthreads();

        const int row0 = ty * 128, col0 = tx * 128;
        const int erow = wm * 64 + (lane >> 2);
        const int ecol = wn * 32 + (lane & 3) * 2;

        if (p.mode == 0) {
            long long coff = zo * p.sCo + zi * p.sCi;
            #pragma unroll
            for (int mt = 0; mt < 4; mt++)
                #pragma unroll
                for (int half = 0; half < 2; half++) {
                    int gr = row0 + erow + mt * 16 + half * 8;
                    long long rb = (long long)gr * p.ldc + col0 + ecol + coff;
                    #pragma unroll
                    for (int nt = 0; nt < 4; nt++) {
                        float2 v;
                        v.x = acc[mt][nt][half * 2 + 0] * p.alpha;
                        v.y = acc[mt][nt][half * 2 + 1] * p.alpha;
                        if (p.Add) {
                            float2 ad = *(const float2*)(p.Add + rb + nt * 8);
                            v.x += ad.x; v.y += ad.y;
                        }
                        *(float2*)(p.C + rb + nt * 8) = v;
                    }
                }
        } else if (p.mode == 3) {
            int b = z >> 4, h = z & 15;
            #pragma unroll
            for (int mt = 0; mt < 4; mt++)
                #pragma unroll
                for (int half = 0; half < 2; half++) {
                    int gr = row0 + erow + mt * 16 + half * 8;
                    long long base = ((long long)(b * CS + gr)) * (3LL * CD)
                                     + h * CAHD + col0 + ecol;
                    #pragma unroll
                    for (int nt = 0; nt < 4; nt++) {
                        float v0 = acc[mt][nt][half * 2 + 0];
                        float v1 = acc[mt][nt][half * 2 + 1];
                        __nv_bfloat16 h0, l0, h1, l1;
                        split2(v0, h0, l0); split2(v1, h1, l1);
                        __nv_bfloat162 hh = __nv_bfloat162(h0, h1);
                        __nv_bfloat162 ll = __nv_bfloat162(l0, l1);
                        __nv_bfloat16* d0 = (__nv_bfloat16*)(p.S3 + base + nt * 8);
                        *(__nv_bfloat162*)(d0)          = hh;
                        *(__nv_bfloat162*)(d0 + CD)     = hh;
                        *(__nv_bfloat162*)(d0 + 2 * CD) = ll;
                    }
                }
        } else {
            #pragma unroll
            for (int mt = 0; mt < 4; mt++)
                #pragma unroll
                for (int half = 0; half < 2; half++) {
                    int gr = row0 + erow + mt * 16 + half * 8;
                    long long rowb = (long long)gr * (3LL * CD);
                    #pragma unroll
                    for (int nt = 0; nt < 4; nt++) {
                        int n = col0 + ecol + nt * 8;
                        int hh_ = n >> 7, d = n & 127;
                        long long base = rowb + hh_ * 384 + d;
                        float v0 = acc[mt][nt][half * 2 + 0];
                        float v1 = acc[mt][nt][half * 2 + 1];
                        __nv_bfloat16 h0, l0, h1, l1;
                        split2(v0, h0, l0); split2(v1, h1, l1);
                        __nv_bfloat162 hv = __nv_bfloat162(h0, h1);
                        __nv_bfloat162 lv = __nv_bfloat162(l0, l1);
                        __nv_bfloat16* dp = p.S3 + base;
                        *(__nv_bfloat162*)(dp)       = hv;
                        *(__nv_bfloat162*)(dp + 128) = (p.mode == 1) ? hv : lv;
                        *(__nv_bfloat162*)(dp + 256) = (p.mode == 1) ? lv : hv;
                    }
                }
        }
    }
}

// =================== elementwise / prep kernels ===================

__global__ void rmsnorm_split_kernel(const float* __restrict__ in, const float* __restrict__ w,
                                     float* __restrict__ outf, __nv_bfloat16* __restrict__ out3,
                                     int Ktot, int colofs) {
    long long row = blockIdx.x;
    const float* ip = in + row * CD;
    float vals[8], ss = 0.f;
    #pragma unroll
    for (int ii = 0; ii < 8; ii++) {
        float u = ip[threadIdx.x + ii * 256];
        vals[ii] = u; ss = fmaf(u, u, ss);
    }
    ss = blockSum(ss);
    float rs = rsqrtf(ss * (1.f / CD) + 1e-6f);
    long long b3 = row * 3LL * Ktot + colofs;
    #pragma unroll
    for (int ii = 0; ii < 8; ii++) {
        int i = threadIdx.x + ii * 256;
        float u = vals[ii] * rs * w[i];
        if (outf) outf[row * CD + i] = u;
        __nv_bfloat16 hi, lo; split2(u, hi, lo);
        out3[b3 + i] = hi;
        out3[b3 + Ktot + i] = hi;
        out3[b3 + 2 * Ktot + i] = lo;
    }
}

__global__ void colmean_kernel(const float* __restrict__ xn, float* __restrict__ xm) {
    int idx = blockIdx.x * blockDim.x + threadIdx.x;
    int b = idx / CD, d = idx % CD;
    float s = 0.f;
    for (int t = 0; t < CS; t++) s += xn[((long long)b * CS + t) * CD + d];
    xm[idx] = s * (1.f / CS);
}

__global__ void mlp2_kernel(const float* __restrict__ xm, const float* __restrict__ wc1,
                            const float* __restrict__ bc1, float* __restrict__ h) {
    int b = blockIdx.y, c = blockIdx.x * 256 + threadIdx.x;
    float s = 0.f;
    for (int k = 0; k < CD; k++) s = fmaf(xm[b * CD + k], wc1[(long long)k * CDQ + c], s);
    s += bc1[c];
    h[b * CDQ + c] = s / (1.f + expf(-s));
}

__global__ void coeff2_kernel(const float* __restrict__ h, const float* __restrict__ wc2,
                              const float* __restrict__ bc2, float* __restrict__ coef) {
    int b = blockIdx.y, c = blockIdx.x * 256 + threadIdx.x;
    float s = 0.f;
    for (int k = 0; k < CDQ; k++) s = fmaf(h[b * CDQ + k], wc2[(long long)k * CNC + c], s);
    s += bc2[c];
    int kdeg = (c / CHD) % CDEG;
    coef[(long long)b * CNC + c] = s * (0.1f / (float)(kdeg + 1));
}

__global__ void coeff3_kernel(const float* __restrict__ coef, const float* __restrict__ wnc,
                              __nv_bfloat16* __restrict__ cf3) {
    int h = blockIdx.x, r = blockIdx.y, i = threadIdx.x;
    float val = 0.f;
    if (r < 16) {
        int b = r >> 2, kd = r & 3;
        val = coef[(long long)b * CNC + (h * 4 + kd) * CHD + i] * wnc[h * CHD + i];
    }
    __nv_bfloat16 hi, lo; split2(val, hi, lo);
    long long base = ((long long)h * 128 + r) * 768;
    cf3[base + i] = hi;
    cf3[base + 256 + i] = hi;
    cf3[base + 512 + i] = lo;
}

__global__ void cheby3_kernel(const float* __restrict__ xn, const float* __restrict__ coef,
                              __nv_bfloat16* __restrict__ kv3, __nv_bfloat16* __restrict__ tsc3) {
    long long bs = blockIdx.x;
    int b = (int)(bs / CS);
    int w = threadIdx.x >> 5, lane = threadIdx.x & 31;
    const float* u = xn + bs * CD + w * CHD;
    float s = 0.f;
    #pragma unroll
    for (int i = lane; i < CHD; i += 32) s += u[i];
    s = warpSum(s);
    float z = tanhf(s * (1.f / CHD));
    float T1 = z, T2 = 2.f * z * z - 1.f, T3 = 2.f * z * T2 - T1;
    const float* cp = coef + (((long long)b * CNH + w) * CDEG) * CHD;
    long long b3 = bs * (3LL * CD) + w * CHD;
    float ssloc = 0.f;
    #pragma unroll
    for (int i = lane; i < CHD; i += 32) {
        float o = cp[i] + T1 * cp[CHD + i] + T2 * cp[2 * CHD + i] + T3 * cp[3 * CHD + i];
        ssloc = fmaf(o, o, ssloc);
        float val = u[i] + o;
        __nv_bfloat16 hi, lo; split2(val, hi, lo);
        kv3[b3 + i] = hi;
        kv3[b3 + CD + i] = hi;
        kv3[b3 + 2 * CD + i] = lo;
    }
    float ss = blockSum(ssloc);
    float rs = rsqrtf(ss * (1.f / CD) + 1e-6f);
    if (lane < 4) {
        float tv = (lane == 0) ? 1.f : (lane == 1) ? T1 : (lane == 2) ? T2 : T3;
        tv *= rs;
        __nv_bfloat16 hi, lo; split2(tv, hi, lo);
        long long base = bs * 96 + w * 4 + lane;
        tsc3[base]      = hi;
        tsc3[base + 32] = hi;
        tsc3[base + 64] = lo;
    }
}

// batched 2048x2048 transpose + B-side split for 5 weights (z selects)
struct T5Params {
    const float* W[5];
    __nv_bfloat16* Y[5];
};
__global__ void transpose_split5_kernel(T5Params p) {
    __shared__ float t[32][33];
    const float* W = p.W[blockIdx.z];
    __nv_bfloat16* Y = p.Y[blockIdx.z];
    int k0 = blockIdx.y * 32, n0 = blockIdx.x * 32;
    int tx = threadIdx.x, ty = threadIdx.y;
    #pragma unroll
    for (int i = 0; i < 4; i++) {
        int k = k0 + ty + i * 8;
        t[ty + i * 8][tx] = W[(long long)k * CD + n0 + tx];
    }
    __syncthreads();
    #pragma unroll
    for (int i = 0; i < 4; i++) {
        int n = n0 + ty + i * 8;
        int k = k0 + tx;
        float a = t[tx][ty + i * 8];
        __nv_bfloat16 hi, lo; split2(a, hi, lo);
        long long base = (long long)n * 3 * CD;
        Y[base + k] = hi;
        Y[base + CD + k] = lo;
        Y[base + 2 * CD + k] = hi;
    }
}

// general transpose + B-side split (used for wfgv bottom)
__global__ void transpose_split_kernel(const float* __restrict__ W, __nv_bfloat16* __restrict__ Y,
                                       int K, int N) {
    __shared__ float t[32][33];
    int k0 = blockIdx.y * 32, n0 = blockIdx.x * 32;
    int tx = threadIdx.x, ty = threadIdx.y;
    #pragma unroll
    for (int i = 0; i < 4; i++) {
        int k = k0 + ty + i * 8;
        t[ty + i * 8][tx] = W[(long long)k * N + n0 + tx];
    }
    __syncthreads();
    #pragma unroll
    for (int i = 0; i < 4; i++) {
        int n = n0 + ty + i * 8;
        int k = k0 + tx;
        float a = t[tx][ty + i * 8];
        __nv_bfloat16 hi, lo; split2(a, hi, lo);
        long long base = (long long)n * 3 * K;
        Y[base + k] = hi;
        Y[base + K + k] = lo;
        Y[base + 2 * K + k] = hi;
    }
}

__global__ void wt1_split_kernel(const float* __restrict__ W, __nv_bfloat16* __restrict__ Y) {
    __shared__ float t[32][33];
    int k0 = blockIdx.y * 32, n0 = blockIdx.x * 32;
    int tx = threadIdx.x, ty = threadIdx.y;
    #pragma unroll
    for (int i = 0; i < 4; i++) {
        int k = k0 + ty + i * 8;
        t[ty + i * 8][tx] = W[(long long)k * (2 * CD) + n0 + tx];
    }
    __syncthreads();
    #pragma unroll
    for (int i = 0; i < 4; i++) {
        int n = n0 + ty + i * 8;
        int k = k0 + tx;
        int h = k >> 8, d = k & 255;
        float a = t[tx][ty + i * 8];
        __nv_bfloat16 hi, lo; split2(a, hi, lo);
        long long base = ((long long)h * (2 * CD) + n) * 768;
        Y[base + d] = hi;
        Y[base + 256 + d] = lo;
        Y[base + 512 + d] = hi;
    }
}

__global__ void cw1t_kernel(const float* __restrict__ CW1, __nv_bfloat16* __restrict__ Y) {
    int n = blockIdx.x * 256 + threadIdx.x;
    int b = blockIdx.y;
    long long obase = ((long long)b * (2 * CD) + n) * 96;
    #pragma unroll
    for (int j = 0; j < 32; j++) {
        int h = j >> 2, kd = j & 3;
        float v = CW1[(((long long)h * 128) + b * 4 + kd) * (2 * CD) + n];
        __nv_bfloat16 hi, lo; split2(v, hi, lo);
        Y[obase + j] = hi;
        Y[obase + 32 + j] = lo;
        Y[obase + 64 + j] = hi;
    }
}

__global__ void vtrans_split_kernel(const float* __restrict__ v, __nv_bfloat16* __restrict__ vt3) {
    __shared__ float t[32][33];
    int bh = blockIdx.z, b = bh >> 4, h = bh & 15;
    int k0 = blockIdx.x * 32, n0 = blockIdx.y * 32;
    int tx = threadIdx.x, ty = threadIdx.y;
    #pragma unroll
    for (int i = 0; i < 4; i++) {
        int k = k0 + ty + i * 8;
        t[ty + i * 8][tx] = v[((long long)(b * CS + k)) * CD + h * CAHD + n0 + tx];
    }
    __syncthreads();
    #pragma unroll
    for (int i = 0; i < 4; i++) {
        int n = n0 + ty + i * 8;
        float a = t[tx][ty + i * 8];
        __nv_bfloat16 hi, lo; split2(a, hi, lo);
        long long base = ((long long)bh * CAHD + n) * (3 * CS);
        vt3[base + k0 + tx] = hi;
        vt3[base + CS + k0 + tx] = lo;
        vt3[base + 2 * CS + k0 + tx] = hi;
    }
}

__global__ void fuse_split_kernel(const float* __restrict__ gv, const float* __restrict__ wnp,
                                  __nv_bfloat16* __restrict__ out3) {
    long long row = blockIdx.x;
    const float* gp = gv + row * (2 * CD);
    float t[8], ss = 0.f;
    #pragma unroll
    for (int ii = 0; ii < 8; ii++) {
        int i = threadIdx.x + ii * 256;
        float g = gp[i], v = gp[CD + i];
        float u = g / (1.f + expf(-g)) * v;
        t[ii] = u; ss = fmaf(u, u, ss);
    }
    ss = blockSum(ss);
    float rs = rsqrtf(ss * (1.f / CD) + 1e-6f);
    long long b3 = row * (3LL * CD);
    #pragma unroll
    for (int ii = 0; ii < 8; ii++) {
        int i = threadIdx.x + ii * 256;
        float u = t[ii] * rs * wnp[i];
        __nv_bfloat16 hi, lo; split2(u, hi, lo);
        out3[b3 + i] = hi;
        out3[b3 + CD + i] = hi;
        out3[b3 + 2 * CD + i] = lo;
    }
}

// ---- causal softmax over 512-wide rows (R6: 256 threads); split probs ----
__global__ void softmax_split_kernel(const float* __restrict__ sc, __nv_bfloat16* __restrict__ p3) {
    long long row = blockIdx.x;
    int i = (int)(row % CS);
    const float* sp = sc + row * CS;
    float e[2];
    float m = -1e30f;
    #pragma unroll
    for (int t = 0; t < 2; t++) { int j = threadIdx.x + t * 256; if (j <= i) m = fmaxf(m, sp[j]); }
    m = blockMax(m);
    float s = 0.f;
    #pragma unroll
    for (int t = 0; t < 2; t++) {
        int j = threadIdx.x + t * 256;
        float ev = (j <= i) ? expf(sp[j] - m) : 0.f;
        e[t] = ev; s += ev;
    }
    s = blockSum(s);
    float inv = 1.f / s;
    long long b3 = row * (3LL * CS);
    #pragma unroll
    for (int t = 0; t < 2; t++) {
        int j = threadIdx.x + t * 256;
        float u = e[t] * inv;
        __nv_bfloat16 hi, lo; split2(u, hi, lo);
        p3[b3 + j] = hi;
        p3[b3 + CS + j] = hi;
        p3[b3 + 2 * CS + j] = lo;
    }
}

// ---------------- host ----------------
static int g_grid = 296;

static void mm(const __nv_bfloat16* A, const __nv_bfloat16* B, float* C, const float* Add,
               __nv_bfloat16* S3, int M, int N, int K3, int lda, int ldb, int ldc, float alpha,
               int bz, int bdiv, long long sAo, long long sAi, long long sBo, long long sBi,
               long long sCo, long long sCi, int mode, int causal) {
    MMParams p;
    p.A = A; p.B = B; p.C = C; p.Add = Add; p.S3 = S3;
    p.lda = lda; p.ldb = ldb; p.ldc = ldc; p.K3 = K3; p.alpha = alpha;
    p.bdiv = bdiv; p.sAo = sAo; p.sAi = sAi; p.sBo = sBo; p.sBi = sBi;
    p.sCo = sCo; p.sCi = sCi;
    p.tilesM = M / 128; p.tilesN = N / 128;
    p.total = bz * p.tilesM * p.tilesN;
    p.mode = mode; p.causal = causal;
    int grid = g_grid < p.total ? g_grid : p.total;
    mm_bf16_kernel<<<grid, 256, MM_SMEM>>>(p);
}

extern "C" void kernel_launch(void* const* d_in, const int* in_sizes, int n_in,
                              void* d_out, int out_size) {
    const float* x     = (const float*)d_in[0];
    const float* w_in  = (const float*)d_in[1];
    const float* wc1   = (const float*)d_in[6];
    const float* bc1   = (const float*)d_in[7];
    const float* wc2   = (const float*)d_in[8];
    const float* bc2   = (const float*)d_in[9];
    const float* wq    = (const float*)d_in[10];
    const float* wk    = (const float*)d_in[11];
    const float* wv    = (const float*)d_in[12];
    const float* wo    = (const float*)d_in[13];
    const float* w_nc  = (const float*)d_in[14];
    const float* w_ns  = (const float*)d_in[15];
    const float* w_fgv = (const float*)d_in[16];
    const float* w_np  = (const float*)d_in[17];
    const float* w_out = (const float*)d_in[18];
    float* out = (float*)d_out;

    int smc = 148;
    cudaDeviceGetAttribute(&smc, cudaDevAttrMultiProcessorCount, 0);
    g_grid = 2 * smc;

    cudaFuncSetAttribute(mm_bf16_kernel, cudaFuncAttributeMaxDynamicSharedMemorySize, MM_SMEM);

    float *xn, *xm, *hs, *coef, *v, *sc, *slr, *gvb, *cw1;
    cudaGetSymbolAddress((void**)&xn,   g_xn);
    cudaGetSymbolAddress((void**)&xm,   g_xmean);
    cudaGetSymbolAddress((void**)&hs,   g_hs);
    cudaGetSymbolAddress((void**)&coef, g_coef);
    cudaGetSymbolAddress((void**)&v,    g_v);
    cudaGetSymbolAddress((void**)&sc,   g_sc);
    cudaGetSymbolAddress((void**)&slr,  g_slr);
    cudaGetSymbolAddress((void**)&gvb,  g_gv);
    cudaGetSymbolAddress((void**)&cw1,  g_cw1);

    __nv_bfloat16 *xn3, *kv3, *attn3, *fus3, *h23, *q3, *k3, *p3, *vt3;
    __nv_bfloat16 *wq3, *wk3, *wv3, *wo3, *wout3, *wfgvb3, *wt13, *cf3, *cw1t3, *tsc3;
    cudaGetSymbolAddress((void**)&xn3,    g3_xn);
    cudaGetSymbolAddress((void**)&kv3,    g3_kv);
    cudaGetSymbolAddress((void**)&attn3,  g3_attn);
    cudaGetSymbolAddress((void**)&fus3,   g3_fus);
    cudaGetSymbolAddress((void**)&h23,    g3_h2);
    cudaGetSymbolAddress((void**)&q3,     g3_q);
    cudaGetSymbolAddress((void**)&k3,     g3_k);
    cudaGetSymbolAddress((void**)&p3,     g3_p);
    cudaGetSymbolAddress((void**)&vt3,    g3_vt);
    cudaGetSymbolAddress((void**)&wq3,    g3_wq);
    cudaGetSymbolAddress((void**)&wk3,    g3_wk);
    cudaGetSymbolAddress((void**)&wv3,    g3_wv);
    cudaGetSymbolAddress((void**)&wo3,    g3_wo);
    cudaGetSymbolAddress((void**)&wout3,  g3_wout);
    cudaGetSymbolAddress((void**)&wfgvb3, g3_wfgvb);
    cudaGetSymbolAddress((void**)&wt13,   g3_wt1);
    cudaGetSymbolAddress((void**)&cf3,    g3_cf);
    cudaGetSymbolAddress((void**)&cw1t3,  g3_cw1t);
    cudaGetSymbolAddress((void**)&tsc3,   g3_tsc);

    dim3 tblk(32, 8);
    {
        T5Params tp;
        tp.W[0] = wq;    tp.Y[0] = wq3;
        tp.W[1] = wk;    tp.Y[1] = wk3;
        tp.W[2] = wv;    tp.Y[2] = wv3;
        tp.W[3] = wo;    tp.Y[3] = wo3;
        tp.W[4] = w_out; tp.Y[4] = wout3;
        transpose_split5_kernel<<<dim3(CD / 32, CD / 32, 5), tblk>>>(tp);
    }
    transpose_split_kernel<<<dim3((2 * CD) / 32, CD / 32), tblk>>>(
        w_fgv + (long long)CD * (2 * CD), wfgvb3, CD, 2 * CD);
    wt1_split_kernel<<<dim3((2 * CD) / 32, CD / 32), tblk>>>(w_fgv, wt13);

    rmsnorm_split_kernel<<<MT, 256>>>(x, w_in, xn, xn3, CD, 0);
    colmean_kernel<<<(CB * CD) / 256, 256>>>(xn, xm);
    mlp2_kernel<<<dim3(CDQ / 256, CB), 256>>>(xm, wc1, bc1, hs);
    coeff2_kernel<<<dim3(CNC / 256, CB), 256>>>(hs, wc2, bc2, coef);
    coeff3_kernel<<<dim3(8, 128), 256>>>(coef, w_nc, cf3);
    cheby3_kernel<<<MT, 256>>>(xn, coef, kv3, tsc3);

    // CW1 = coeff3 @ WT1 (batched over 8 heads)
    mm(cf3, wt13, cw1, 0, 0, 128, 2 * CD, 768, 768, 768, 2 * CD, 1.f,
       8, 1, (long long)128 * 768, 0, (long long)(2 * CD) * 768, 0,
       (long long)128 * (2 * CD), 0, 0, 0);
    cw1t_kernel<<<dim3((2 * CD) / 256, CB), 256>>>(cw1, cw1t3);

    // q/k projections -> head-split epilogues; v -> fp32
    mm(xn3, wq3, 0, 0, q3, MT, CD, 3 * CD, 3 * CD, 3 * CD, CD, 1.f,
       1, 1, 0, 0, 0, 0, 0, 0, 1, 0);
    mm(kv3, wk3, 0, 0, k3, MT, CD, 3 * CD, 3 * CD, 3 * CD, CD, 1.f,
       1, 1, 0, 0, 0, 0, 0, 0, 2, 0);
    mm(kv3, wv3, v, 0, 0, MT, CD, 3 * CD, 3 * CD, 3 * CD, CD, 1.f,
       1, 1, 0, 0, 0, 0, 0, 0, 0, 0);

    vtrans_split_kernel<<<dim3(CS / 32, CAHD / 32, CB * CAH), tblk>>>(v, vt3);

    // scores = q @ k^T / sqrt(hd) with causal tile skip
    mm(q3, k3, sc, 0, 0, CS, CS, 384, 3 * CD, 3 * CD, CS, 0.08838834764831845f,
       CB * CAH, CAH,
       (long long)CS * 3 * CD, 384,
       (long long)CS * 3 * CD, 384,
       (long long)CAH * CS * CS, (long long)CS * CS, 0, 1);

    softmax_split_kernel<<<CB * CAH * CS, 256>>>(sc, p3);

    // attn = P @ V -> attn3 split epilogue
    mm(p3, vt3, 0, 0, attn3, CS, CAHD, 3 * CS, 3 * CS, 3 * CS, CD, 1.f,
       CB * CAH, CAH,
       (long long)CAH * CS * 3 * CS, (long long)CS * 3 * CS,
       (long long)CAH * CAHD * 3 * CS, (long long)CAHD * 3 * CS,
       0, 0, 3, 0);

    // slr = attn @ wo
    mm(attn3, wo3, slr, 0, 0, MT, CD, 3 * CD, 3 * CD, 3 * CD, CD, 1.f,
       1, 1, 0, 0, 0, 0, 0, 0, 0, 0);

    // h2 = split(rmsnorm(slr, w_ns))
    rmsnorm_split_kernel<<<MT, 256>>>(slr, w_ns, 0, h23, CD, 0);

    // gv = (rs*T) @ CW1^T  (low-rank h1 path)
    mm(tsc3, cw1t3, gvb, 0, 0, CS, 2 * CD, 96, 96, 96, 2 * CD, 1.f,
       CB, 1, (long long)CS * 96, 0, (long long)(2 * CD) * 96, 0,
       (long long)CS * (2 * CD), 0, 0, 0);
    // gv += h2 @ wfgv_bottom
    mm(h23, wfgvb3, gvb, gvb, 0, MT, 2 * CD, 3 * CD, 3 * CD, 3 * CD, 2 * CD, 1.f,
       1, 1, 0, 0, 0, 0, 0, 0, 0, 0);

    fuse_split_kernel<<<MT, 256>>>(gvb, w_np, fus3);
    // out = x + fused @ w_out
    mm(fus3, wout3, out, x, 0, MT, CD, 3 * CD, 3 * CD, 3 * CD, CD, 1.f,
       1, 1, 0, 0, 0, 0, 0, 0, 0, 0);
}

// round 14
// speedup vs baseline: 1.0004x; 1.0004x over previous
#include <cuda_runtime.h>
#include <cuda_bf16.h>
#include <cstdint>
#include <math.h>

// ---------------- problem constants ----------------
#define CB   4
#define CS   512
#define CD   2048
#define CNH  8
#define CDEG 4
#define CHD  256
#define CAH  16
#define CAHD 128
#define CDQ  512
#define CNC  (CNH*CDEG*CHD)   // 8192
#define MT   (CB*CS)          // 2048 tokens

// ---------------- fp32 scratch ----------------
__device__ float g_xn   [MT*CD];
__device__ float g_xmean[CB*CD];
__device__ float g_hs   [CB*CDQ];
__device__ float g_coef [CB*CNC];
__device__ float g_v    [MT*CD];
__device__ float g_sc   [(size_t)CB*CAH*CS*CS];
__device__ float g_slr  [MT*CD];
__device__ float g_gv   [MT*2*CD];
__device__ float g_cw1  [(size_t)8*128*(2*CD)];

// ---------------- bf16 split scratch (3x K) ----------------
__device__ __align__(16) __nv_bfloat16 g3_xn   [MT*3*CD];
__device__ __align__(16) __nv_bfloat16 g3_kv   [MT*3*CD];
__device__ __align__(16) __nv_bfloat16 g3_attn [MT*3*CD];
__device__ __align__(16) __nv_bfloat16 g3_fus  [MT*3*CD];
__device__ __align__(16) __nv_bfloat16 g3_h2   [(size_t)MT*3*CD];
__device__ __align__(16) __nv_bfloat16 g3_q    [MT*3*CD];
__device__ __align__(16) __nv_bfloat16 g3_k    [MT*3*CD];
__device__ __align__(16) __nv_bfloat16 g3_p    [(size_t)CB*CAH*CS*3*CS];
__device__ __align__(16) __nv_bfloat16 g3_vt   [(size_t)CB*CAH*CAHD*3*CS];
__device__ __align__(16) __nv_bfloat16 g3_wq   [(size_t)CD*3*CD];
__device__ __align__(16) __nv_bfloat16 g3_wk   [(size_t)CD*3*CD];
__device__ __align__(16) __nv_bfloat16 g3_wv   [(size_t)CD*3*CD];
__device__ __align__(16) __nv_bfloat16 g3_wo   [(size_t)CD*3*CD];
__device__ __align__(16) __nv_bfloat16 g3_wout [(size_t)CD*3*CD];
__device__ __align__(16) __nv_bfloat16 g3_wfgvb[(size_t)(2*CD)*3*CD];
__device__ __align__(16) __nv_bfloat16 g3_wt1  [(size_t)8*(2*CD)*768];
__device__ __align__(16) __nv_bfloat16 g3_cf   [(size_t)8*128*768];
__device__ __align__(16) __nv_bfloat16 g3_cw1t [(size_t)CB*(2*CD)*96];
__device__ __align__(16) __nv_bfloat16 g3_tsc  [(size_t)MT*96];

// ---------------- helpers ----------------
__device__ __forceinline__ uint32_t smem_u32(const void* p) {
    uint32_t a;
    asm("{ .reg .u64 t; cvta.to.shared.u64 t, %1; cvt.u32.u64 %0, t; }" : "=r"(a) : "l"(p));
    return a;
}
__device__ __forceinline__ void cp16(uint32_t dst, const void* src) {
    asm volatile("cp.async.cg.shared.global [%0], [%1], 16;" :: "r"(dst), "l"(src) : "memory");
}
__device__ __forceinline__ void cp_commit() { asm volatile("cp.async.commit_group;" ::: "memory"); }

__device__ __forceinline__ void ldm_x4(uint32_t addr, uint32_t& r0, uint32_t& r1,
                                       uint32_t& r2, uint32_t& r3) {
    asm volatile("ldmatrix.sync.aligned.m8n8.x4.shared.b16 {%0,%1,%2,%3}, [%4];"
                 : "=r"(r0), "=r"(r1), "=r"(r2), "=r"(r3) : "r"(addr));
}
__device__ __forceinline__ void mma16816(float* c, const uint32_t* a, const uint32_t* b) {
    asm volatile("mma.sync.aligned.m16n8k16.row.col.f32.bf16.bf16.f32 "
                 "{%0,%1,%2,%3}, {%4,%5,%6,%7}, {%8,%9}, {%0,%1,%2,%3};"
                 : "+f"(c[0]), "+f"(c[1]), "+f"(c[2]), "+f"(c[3])
                 : "r"(a[0]), "r"(a[1]), "r"(a[2]), "r"(a[3]), "r"(b[0]), "r"(b[1]));
}

__device__ __forceinline__ void split2(float a, __nv_bfloat16& hi, __nv_bfloat16& lo) {
    hi = __float2bfloat16(a);
    lo = __float2bfloat16(a - __bfloat162float(hi));
}

// ---------------- reductions (blockDim == 256) ----------------
__device__ __forceinline__ float warpSum(float v) {
    #pragma unroll
    for (int o = 16; o > 0; o >>= 1) v += __shfl_xor_sync(0xffffffffu, v, o);
    return v;
}
__device__ __forceinline__ float warpMax(float v) {
    #pragma unroll
    for (int o = 16; o > 0; o >>= 1) v = fmaxf(v, __shfl_xor_sync(0xffffffffu, v, o));
    return v;
}
__device__ __forceinline__ float blockSum(float v) {
    __shared__ float sh[8];
    v = warpSum(v);
    __syncthreads();
    if ((threadIdx.x & 31) == 0) sh[threadIdx.x >> 5] = v;
    __syncthreads();
    float r = sh[0];
    #pragma unroll
    for (int i = 1; i < 8; i++) r += sh[i];
    return r;
}
__device__ __forceinline__ float blockMax(float v) {
    __shared__ float shm[8];
    v = warpMax(v);
    __syncthreads();
    if ((threadIdx.x & 31) == 0) shm[threadIdx.x >> 5] = v;
    __syncthreads();
    float r = shm[0];
    #pragma unroll
    for (int i = 1; i < 8; i++) r = fmaxf(r, shm[i]);
    return r;
}

// =================== persistent HMMA bf16 GEMM (R6, FROZEN) ================
#define ROWB 80
#define TILEB (128*ROWB)
#define STGB  (2*TILEB)
#define NSTG  4
#define MM_SMEM (NSTG*STGB)  // 81920

struct MMParams {
    const __nv_bfloat16* A;
    const __nv_bfloat16* B;
    float* C;
    const float* Add;
    __nv_bfloat16* S3;
    int lda, ldb, ldc, K3;
    float alpha;
    int bdiv;
    long long sAo, sAi, sBo, sBi, sCo, sCi;
    int tilesM, tilesN, total;
    int mode;        // 0 fp32 C(+Add); 1 q3 split; 2 k3 split; 3 attn3 split
    int causal;
};

__global__ void __launch_bounds__(256, 2)
mm_bf16_kernel(MMParams p) {
    extern __shared__ __align__(128) char sm[];

    const int tid  = threadIdx.x, lane = tid & 31, wid = tid >> 5;
    const int wm   = wid >> 2, wn = wid & 3;
    const uint32_t sbase = smem_u32(sm);
    const int lrow = tid >> 1;
    const int lch  = (tid & 1) * 2;
    const uint32_t sAw = sbase + lrow * ROWB + lch * 16;
    const uint32_t sBw = sAw + TILEB;
    const int lr15 = lane & 15, lhi = lane >> 4;
    const uint32_t aoff = (uint32_t)((wm * 64 + lr15) * ROWB + lhi * 16);
    const uint32_t boff = (uint32_t)((wn * 32 + lr15) * ROWB + lhi * 16) + TILEB;
    const int tilesMN = p.tilesM * p.tilesN;
    const int NK = p.K3 / 32;

    for (int t = blockIdx.x; t < p.total; t += gridDim.x) {
        int z  = t / tilesMN;
        int r  = t - z * tilesMN;
        int ty = r / p.tilesN, tx = r - ty * p.tilesN;
        if (p.causal && tx > ty) continue;
        int zo = z / p.bdiv, zi = z - zo * p.bdiv;

        const __nv_bfloat16* Agb = p.A + zo * p.sAo + zi * p.sAi
                                   + (long long)(ty * 128 + lrow) * p.lda + lch * 8;
        const __nv_bfloat16* Bgb = p.B + zo * p.sBo + zi * p.sBi
                                   + (long long)(tx * 128 + lrow) * p.ldb + lch * 8;

        float acc[4][4][4];
        #pragma unroll
        for (int i = 0; i < 4; i++)
            #pragma unroll
            for (int j = 0; j < 4; j++)
                #pragma unroll
                for (int e = 0; e < 4; e++) acc[i][j][e] = 0.f;

        #pragma unroll
        for (int s = 0; s < 3; s++) {
            uint32_t o = (uint32_t)s * STGB;
            const __nv_bfloat16* Ag = Agb + s * 32;
            const __nv_bfloat16* Bg = Bgb + s * 32;
            cp16(sAw + o,      Ag);
            cp16(sAw + o + 16, Ag + 8);
            cp16(sBw + o,      Bg);
            cp16(sBw + o + 16, Bg + 8);
            cp_commit();
        }

        for (int kc = 0; kc < NK; kc++) {
            asm volatile("cp.async.wait_group 2;" ::: "memory");
            __syncthreads();
            if (kc + 3 < NK) {
                uint32_t o = (uint32_t)((kc + 3) & 3) * STGB;
                const __nv_bfloat16* Ag = Agb + (kc + 3) * 32;
                const __nv_bfloat16* Bg = Bgb + (kc + 3) * 32;
                cp16(sAw + o,      Ag);
                cp16(sAw + o + 16, Ag + 8);
                cp16(sBw + o,      Bg);
                cp16(sBw + o + 16, Bg + 8);
            }
            cp_commit();

            uint32_t sA = sbase + (uint32_t)(kc & 3) * STGB + aoff;
            uint32_t sB = sbase + (uint32_t)(kc & 3) * STGB + boff;
            #pragma unroll
            for (int ks = 0; ks < 2; ks++) {
                uint32_t a[4][4];
                #pragma unroll
                for (int mt = 0; mt < 4; mt++)
                    ldm_x4(sA + mt * (16 * ROWB) + ks * 32, a[mt][0], a[mt][1], a[mt][2], a[mt][3]);
                uint32_t b[4][2];
                #pragma unroll
                for (int bt = 0; bt < 2; bt++) {
                    uint32_t r0, r1, r2, r3;
                    ldm_x4(sB + bt * (16 * ROWB) + ks * 32, r0, r1, r2, r3);
                    b[bt * 2 + 0][0] = r0; b[bt * 2 + 0][1] = r2;
                    b[bt * 2 + 1][0] = r1; b[bt * 2 + 1][1] = r3;
                }
                #pragma unroll
                for (int mt = 0; mt < 4; mt++)
                    #pragma unroll
                    for (int nt = 0; nt < 4; nt++)
                        mma16816(acc[mt][nt], a[mt], b[nt]);
            }
        }
        __syncthreads();

        const int row0 = ty * 128, col0 = tx * 128;
        const int erow = wm * 64 + (lane >> 2);
        const int ecol = wn * 32 + (lane & 3) * 2;

        if (p.mode == 0) {
            long long coff = zo * p.sCo + zi * p.sCi;
            #pragma unroll
            for (int mt = 0; mt < 4; mt++)
                #pragma unroll
                for (int half = 0; half < 2; half++) {
                    int gr = row0 + erow + mt * 16 + half * 8;
                    long long rb = (long long)gr * p.ldc + col0 + ecol + coff;
                    #pragma unroll
                    for (int nt = 0; nt < 4; nt++) {
                        float2 v;
                        v.x = acc[mt][nt][half * 2 + 0] * p.alpha;
                        v.y = acc[mt][nt][half * 2 + 1] * p.alpha;
                        if (p.Add) {
                            float2 ad = *(const float2*)(p.Add + rb + nt * 8);
                            v.x += ad.x; v.y += ad.y;
                        }
                        *(float2*)(p.C + rb + nt * 8) = v;
                    }
                }
        } else if (p.mode == 3) {
            int b = z >> 4, h = z & 15;
            #pragma unroll
            for (int mt = 0; mt < 4; mt++)
                #pragma unroll
                for (int half = 0; half < 2; half++) {
                    int gr = row0 + erow + mt * 16 + half * 8;
                    long long base = ((long long)(b * CS + gr)) * (3LL * CD)
                                     + h * CAHD + col0 + ecol;
                    #pragma unroll
                    for (int nt = 0; nt < 4; nt++) {
                        float v0 = acc[mt][nt][half * 2 + 0];
                        float v1 = acc[mt][nt][half * 2 + 1];
                        __nv_bfloat16 h0, l0, h1, l1;
                        split2(v0, h0, l0); split2(v1, h1, l1);
                        __nv_bfloat162 hh = __nv_bfloat162(h0, h1);
                        __nv_bfloat162 ll = __nv_bfloat162(l0, l1);
                        __nv_bfloat16* d0 = (__nv_bfloat16*)(p.S3 + base + nt * 8);
                        *(__nv_bfloat162*)(d0)          = hh;
                        *(__nv_bfloat162*)(d0 + CD)     = hh;
                        *(__nv_bfloat162*)(d0 + 2 * CD) = ll;
                    }
                }
        } else {
            #pragma unroll
            for (int mt = 0; mt < 4; mt++)
                #pragma unroll
                for (int half = 0; half < 2; half++) {
                    int gr = row0 + erow + mt * 16 + half * 8;
                    long long rowb = (long long)gr * (3LL * CD);
                    #pragma unroll
                    for (int nt = 0; nt < 4; nt++) {
                        int n = col0 + ecol + nt * 8;
                        int hh_ = n >> 7, d = n & 127;
                        long long base = rowb + hh_ * 384 + d;
                        float v0 = acc[mt][nt][half * 2 + 0];
                        float v1 = acc[mt][nt][half * 2 + 1];
                        __nv_bfloat16 h0, l0, h1, l1;
                        split2(v0, h0, l0); split2(v1, h1, l1);
                        __nv_bfloat162 hv = __nv_bfloat162(h0, h1);
                        __nv_bfloat162 lv = __nv_bfloat162(l0, l1);
                        __nv_bfloat16* dp = p.S3 + base;
                        *(__nv_bfloat162*)(dp)       = hv;
                        *(__nv_bfloat162*)(dp + 128) = (p.mode == 1) ? hv : lv;
                        *(__nv_bfloat162*)(dp + 256) = (p.mode == 1) ? lv : hv;
                    }
                }
        }
    }
}

// =================== elementwise / prep kernels ===================

// rmsnorm -> fp32 out (optional) + A-side split (hi,hi,lo); vectorized pairs
__global__ void rmsnorm_split_kernel(const float* __restrict__ in, const float* __restrict__ w,
                                     float* __restrict__ outf, __nv_bfloat16* __restrict__ out3,
                                     int Ktot, int colofs) {
    long long row = blockIdx.x;
    const float2* ip2 = (const float2*)(in + row * CD);
    const float2* w2  = (const float2*)w;
    float2 vals[4];
    float ss = 0.f;
    #pragma unroll
    for (int ii = 0; ii < 4; ii++) {
        int p = threadIdx.x + ii * 256;
        float2 u = ip2[p];
        vals[ii] = u;
        ss = fmaf(u.x, u.x, ss);
        ss = fmaf(u.y, u.y, ss);
    }
    ss = blockSum(ss);
    float rs = rsqrtf(ss * (1.f / CD) + 1e-6f);
    long long b3 = row * 3LL * Ktot + colofs;
    #pragma unroll
    for (int ii = 0; ii < 4; ii++) {
        int p = threadIdx.x + ii * 256;
        float2 wv = w2[p];
        float ux = vals[ii].x * rs * wv.x;
        float uy = vals[ii].y * rs * wv.y;
        if (outf) ((float2*)(outf + row * CD))[p] = make_float2(ux, uy);
        __nv_bfloat16 hx, lx, hy, ly;
        split2(ux, hx, lx); split2(uy, hy, ly);
        __nv_bfloat162 hv(hx, hy), lv(lx, ly);
        __nv_bfloat16* dp = out3 + b3 + 2 * p;
        *(__nv_bfloat162*)(dp)            = hv;
        *(__nv_bfloat162*)(dp + Ktot)     = hv;
        *(__nv_bfloat162*)(dp + 2 * Ktot) = lv;
    }
}

__global__ void colmean_kernel(const float* __restrict__ xn, float* __restrict__ xm) {
    int idx = blockIdx.x * blockDim.x + threadIdx.x;
    int b = idx / CD, d = idx % CD;
    float s = 0.f;
    for (int t = 0; t < CS; t++) s += xn[((long long)b * CS + t) * CD + d];
    xm[idx] = s * (1.f / CS);
}

__global__ void mlp2_kernel(const float* __restrict__ xm, const float* __restrict__ wc1,
                            const float* __restrict__ bc1, float* __restrict__ h) {
    int b = blockIdx.y, c = blockIdx.x * 256 + threadIdx.x;
    float s = 0.f;
    for (int k = 0; k < CD; k++) s = fmaf(xm[b * CD + k], wc1[(long long)k * CDQ + c], s);
    s += bc1[c];
    h[b * CDQ + c] = s / (1.f + expf(-s));
}

__global__ void coeff2_kernel(const float* __restrict__ h, const float* __restrict__ wc2,
                              const float* __restrict__ bc2, float* __restrict__ coef) {
    int b = blockIdx.y, c = blockIdx.x * 256 + threadIdx.x;
    float s = 0.f;
    for (int k = 0; k < CDQ; k++) s = fmaf(h[b * CDQ + k], wc2[(long long)k * CNC + c], s);
    s += bc2[c];
    int kdeg = (c / CHD) % CDEG;
    coef[(long long)b * CNC + c] = s * (0.1f / (float)(kdeg + 1));
}

__global__ void coeff3_kernel(const float* __restrict__ coef, const float* __restrict__ wnc,
                              __nv_bfloat16* __restrict__ cf3) {
    int h = blockIdx.x, r = blockIdx.y, i = threadIdx.x;
    float val = 0.f;
    if (r < 16) {
        int b = r >> 2, kd = r & 3;
        val = coef[(long long)b * CNC + (h * 4 + kd) * CHD + i] * wnc[h * CHD + i];
    }
    __nv_bfloat16 hi, lo; split2(val, hi, lo);
    long long base = ((long long)h * 128 + r) * 768;
    cf3[base + i] = hi;
    cf3[base + 256 + i] = hi;
    cf3[base + 512 + i] = lo;
}

// cheby: kv split vectorized (pairs); tsc3 unchanged
__global__ void cheby3_kernel(const float* __restrict__ xn, const float* __restrict__ coef,
                              __nv_bfloat16* __restrict__ kv3, __nv_bfloat16* __restrict__ tsc3) {
    long long bs = blockIdx.x;
    int b = (int)(bs / CS);
    int w = threadIdx.x >> 5, lane = threadIdx.x & 31;
    const float2* u2 = (const float2*)(xn + bs * CD + w * CHD);
    float s = 0.f;
    #pragma unroll
    for (int pass = 0; pass < 4; pass++) {
        float2 u = u2[lane + pass * 32];
        s += u.x + u.y;
    }
    s = warpSum(s);
    float z = tanhf(s * (1.f / CHD));
    float T1 = z, T2 = 2.f * z * z - 1.f, T3 = 2.f * z * T2 - T1;
    const float2* cp2 = (const float2*)(coef + (((long long)b * CNH + w) * CDEG) * CHD);
    long long b3 = bs * (3LL * CD) + w * CHD;
    float ssloc = 0.f;
    #pragma unroll
    for (int pass = 0; pass < 4; pass++) {
        int p = lane + pass * 32;            // pair index 0..127
        float2 c0 = cp2[p];
        float2 c1 = cp2[128 + p];
        float2 c2 = cp2[256 + p];
        float2 c3 = cp2[384 + p];
        float2 u  = u2[p];
        float ox = c0.x + T1 * c1.x + T2 * c2.x + T3 * c3.x;
        float oy = c0.y + T1 * c1.y + T2 * c2.y + T3 * c3.y;
        ssloc = fmaf(ox, ox, ssloc);
        ssloc = fmaf(oy, oy, ssloc);
        float vx = u.x + ox, vy = u.y + oy;
        __nv_bfloat16 hx, lx, hy, ly;
        split2(vx, hx, lx); split2(vy, hy, ly);
        __nv_bfloat162 hv(hx, hy), lv(lx, ly);
        __nv_bfloat16* dp = kv3 + b3 + 2 * p;
        *(__nv_bfloat162*)(dp)          = hv;
        *(__nv_bfloat162*)(dp + CD)     = hv;
        *(__nv_bfloat162*)(dp + 2 * CD) = lv;
    }
    float ss = blockSum(ssloc);
    float rs = rsqrtf(ss * (1.f / CD) + 1e-6f);
    if (lane < 4) {
        float tv = (lane == 0) ? 1.f : (lane == 1) ? T1 : (lane == 2) ? T2 : T3;
        tv *= rs;
        __nv_bfloat16 hi, lo; split2(tv, hi, lo);
        long long base = bs * 96 + w * 4 + lane;
        tsc3[base]      = hi;
        tsc3[base + 32] = hi;
        tsc3[base + 64] = lo;
    }
}

// batched 2048x2048 transpose + B-side split for 5 weights (z selects)
struct T5Params {
    const float* W[5];
    __nv_bfloat16* Y[5];
};
__global__ void transpose_split5_kernel(T5Params p) {
    __shared__ float t[32][33];
    const float* W = p.W[blockIdx.z];
    __nv_bfloat16* Y = p.Y[blockIdx.z];
    int k0 = blockIdx.y * 32, n0 = blockIdx.x * 32;
    int tx = threadIdx.x, ty = threadIdx.y;
    #pragma unroll
    for (int i = 0; i < 4; i++) {
        int k = k0 + ty + i * 8;
        t[ty + i * 8][tx] = W[(long long)k * CD + n0 + tx];
    }
    __syncthreads();
    #pragma unroll
    for (int i = 0; i < 4; i++) {
        int n = n0 + ty + i * 8;
        int k = k0 + tx;
        float a = t[tx][ty + i * 8];
        __nv_bfloat16 hi, lo; split2(a, hi, lo);
        long long base = (long long)n * 3 * CD;
        Y[base + k] = hi;
        Y[base + CD + k] = lo;
        Y[base + 2 * CD + k] = hi;
    }
}

// general transpose + B-side split (used for wfgv bottom)
__global__ void transpose_split_kernel(const float* __restrict__ W, __nv_bfloat16* __restrict__ Y,
                                       int K, int N) {
    __shared__ float t[32][33];
    int k0 = blockIdx.y * 32, n0 = blockIdx.x * 32;
    int tx = threadIdx.x, ty = threadIdx.y;
    #pragma unroll
    for (int i = 0; i < 4; i++) {
        int k = k0 + ty + i * 8;
        t[ty + i * 8][tx] = W[(long long)k * N + n0 + tx];
    }
    __syncthreads();
    #pragma unroll
    for (int i = 0; i < 4; i++) {
        int n = n0 + ty + i * 8;
        int k = k0 + tx;
        float a = t[tx][ty + i * 8];
        __nv_bfloat16 hi, lo; split2(a, hi, lo);
        long long base = (long long)n * 3 * K;
        Y[base + k] = hi;
        Y[base + K + k] = lo;
        Y[base + 2 * K + k] = hi;
    }
}

__global__ void wt1_split_kernel(const float* __restrict__ W, __nv_bfloat16* __restrict__ Y) {
    __shared__ float t[32][33];
    int k0 = blockIdx.y * 32, n0 = blockIdx.x * 32;
    int tx = threadIdx.x, ty = threadIdx.y;
    #pragma unroll
    for (int i = 0; i < 4; i++) {
        int k = k0 + ty + i * 8;
        t[ty + i * 8][tx] = W[(long long)k * (2 * CD) + n0 + tx];
    }
    __syncthreads();
    #pragma unroll
    for (int i = 0; i < 4; i++) {
        int n = n0 + ty + i * 8;
        int k = k0 + tx;
        int h = k >> 8, d = k & 255;
        float a = t[tx][ty + i * 8];
        __nv_bfloat16 hi, lo; split2(a, hi, lo);
        long long base = ((long long)h * (2 * CD) + n) * 768;
        Y[base + d] = hi;
        Y[base + 256 + d] = lo;
        Y[base + 512 + d] = hi;
    }
}

__global__ void cw1t_kernel(const float* __restrict__ CW1, __nv_bfloat16* __restrict__ Y) {
    int n = blockIdx.x * 256 + threadIdx.x;
    int b = blockIdx.y;
    long long obase = ((long long)b * (2 * CD) + n) * 96;
    #pragma unroll
    for (int j = 0; j < 32; j++) {
        int h = j >> 2, kd = j & 3;
        float v = CW1[(((long long)h * 128) + b * 4 + kd) * (2 * CD) + n];
        __nv_bfloat16 hi, lo; split2(v, hi, lo);
        Y[obase + j] = hi;
        Y[obase + 32 + j] = lo;
        Y[obase + 64 + j] = hi;
    }
}

__global__ void vtrans_split_kernel(const float* __restrict__ v, __nv_bfloat16* __restrict__ vt3) {
    __shared__ float t[32][33];
    int bh = blockIdx.z, b = bh >> 4, h = bh & 15;
    int k0 = blockIdx.x * 32, n0 = blockIdx.y * 32;
    int tx = threadIdx.x, ty = threadIdx.y;
    #pragma unroll
    for (int i = 0; i < 4; i++) {
        int k = k0 + ty + i * 8;
        t[ty + i * 8][tx] = v[((long long)(b * CS + k)) * CD + h * CAHD + n0 + tx];
    }
    __syncthreads();
    #pragma unroll
    for (int i = 0; i < 4; i++) {
        int n = n0 + ty + i * 8;
        float a = t[tx][ty + i * 8];
        __nv_bfloat16 hi, lo; split2(a, hi, lo);
        long long base = ((long long)bh * CAHD + n) * (3 * CS);
        vt3[base + k0 + tx] = hi;
        vt3[base + CS + k0 + tx] = lo;
        vt3[base + 2 * CS + k0 + tx] = hi;
    }
}

// fused = rmsnorm(silu(g)*v, w_np) -> A-side split; vectorized pairs
__global__ void fuse_split_kernel(const float* __restrict__ gv, const float* __restrict__ wnp,
                                  __nv_bfloat16* __restrict__ out3) {
    long long row = blockIdx.x;
    const float2* gp2 = (const float2*)(gv + row * (2 * CD));
    const float2* w2  = (const float2*)wnp;
    float2 t[4];
    float ss = 0.f;
    #pragma unroll
    for (int ii = 0; ii < 4; ii++) {
        int p = threadIdx.x + ii * 256;
        float2 g = gp2[p];
        float2 v = gp2[CD / 2 + p];
        float ux = g.x / (1.f + expf(-g.x)) * v.x;
        float uy = g.y / (1.f + expf(-g.y)) * v.y;
        t[ii] = make_float2(ux, uy);
        ss = fmaf(ux, ux, ss);
        ss = fmaf(uy, uy, ss);
    }
    ss = blockSum(ss);
    float rs = rsqrtf(ss * (1.f / CD) + 1e-6f);
    long long b3 = row * (3LL * CD);
    #pragma unroll
    for (int ii = 0; ii < 4; ii++) {
        int p = threadIdx.x + ii * 256;
        float2 wv = w2[p];
        float ux = t[ii].x * rs * wv.x;
        float uy = t[ii].y * rs * wv.y;
        __nv_bfloat16 hx, lx, hy, ly;
        split2(ux, hx, lx); split2(uy, hy, ly);
        __nv_bfloat162 hv(hx, hy), lv(lx, ly);
        __nv_bfloat16* dp = out3 + b3 + 2 * p;
        *(__nv_bfloat162*)(dp)          = hv;
        *(__nv_bfloat162*)(dp + CD)     = hv;
        *(__nv_bfloat162*)(dp + 2 * CD) = lv;
    }
}

// causal softmax over 512-wide rows; vectorized pairs; split probs
__global__ void softmax_split_kernel(const float* __restrict__ sc, __nv_bfloat16* __restrict__ p3) {
    long long row = blockIdx.x;
    int i = (int)(row % CS);
    const float2* sp2 = (const float2*)(sc + row * CS);
    int j2 = threadIdx.x;             // pair index; cols 2j2, 2j2+1
    int c0 = 2 * j2, c1 = 2 * j2 + 1;
    float2 sv = make_float2(0.f, 0.f);
    float m = -1e30f;
    if (c0 <= i) {
        sv = sp2[j2];
        m = fmaxf(m, sv.x);
        if (c1 <= i) m = fmaxf(m, sv.y);
    }
    m = blockMax(m);
    float ex = (c0 <= i) ? expf(sv.x - m) : 0.f;
    float ey = (c1 <= i) ? expf(sv.y - m) : 0.f;
    float s = blockSum(ex + ey);
    float inv = 1.f / s;
    float ux = ex * inv, uy = ey * inv;
    __nv_bfloat16 hx, lx, hy, ly;
    split2(ux, hx, lx); split2(uy, hy, ly);
    __nv_bfloat162 hv(hx, hy), lv(lx, ly);
    long long b3 = row * (3LL * CS);
    __nv_bfloat16* dp = p3 + b3 + c0;
    *(__nv_bfloat162*)(dp)          = hv;
    *(__nv_bfloat162*)(dp + CS)     = hv;
    *(__nv_bfloat162*)(dp + 2 * CS) = lv;
}

// ---------------- host ----------------
static int g_grid = 296;

static void mm(const __nv_bfloat16* A, const __nv_bfloat16* B, float* C, const float* Add,
               __nv_bfloat16* S3, int M, int N, int K3, int lda, int ldb, int ldc, float alpha,
               int bz, int bdiv, long long sAo, long long sAi, long long sBo, long long sBi,
               long long sCo, long long sCi, int mode, int causal) {
    MMParams p;
    p.A = A; p.B = B; p.C = C; p.Add = Add; p.S3 = S3;
    p.lda = lda; p.ldb = ldb; p.ldc = ldc; p.K3 = K3; p.alpha = alpha;
    p.bdiv = bdiv; p.sAo = sAo; p.sAi = sAi; p.sBo = sBo; p.sBi = sBi;
    p.sCo = sCo; p.sCi = sCi;
    p.tilesM = M / 128; p.tilesN = N / 128;
    p.total = bz * p.tilesM * p.tilesN;
    p.mode = mode; p.causal = causal;
    int grid = g_grid < p.total ? g_grid : p.total;
    mm_bf16_kernel<<<grid, 256, MM_SMEM>>>(p);
}

extern "C" void kernel_launch(void* const* d_in, const int* in_sizes, int n_in,
                              void* d_out, int out_size) {
    const float* x     = (const float*)d_in[0];
    const float* w_in  = (const float*)d_in[1];
    const float* wc1   = (const float*)d_in[6];
    const float* bc1   = (const float*)d_in[7];
    const float* wc2   = (const float*)d_in[8];
    const float* bc2   = (const float*)d_in[9];
    const float* wq    = (const float*)d_in[10];
    const float* wk    = (const float*)d_in[11];
    const float* wv    = (const float*)d_in[12];
    const float* wo    = (const float*)d_in[13];
    const float* w_nc  = (const float*)d_in[14];
    const float* w_ns  = (const float*)d_in[15];
    const float* w_fgv = (const float*)d_in[16];
    const float* w_np  = (const float*)d_in[17];
    const float* w_out = (const float*)d_in[18];
    float* out = (float*)d_out;

    int smc = 148;
    cudaDeviceGetAttribute(&smc, cudaDevAttrMultiProcessorCount, 0);
    g_grid = 2 * smc;

    cudaFuncSetAttribute(mm_bf16_kernel, cudaFuncAttributeMaxDynamicSharedMemorySize, MM_SMEM);

    float *xn, *xm, *hs, *coef, *v, *sc, *slr, *gvb, *cw1;
    cudaGetSymbolAddress((void**)&xn,   g_xn);
    cudaGetSymbolAddress((void**)&xm,   g_xmean);
    cudaGetSymbolAddress((void**)&hs,   g_hs);
    cudaGetSymbolAddress((void**)&coef, g_coef);
    cudaGetSymbolAddress((void**)&v,    g_v);
    cudaGetSymbolAddress((void**)&sc,   g_sc);
    cudaGetSymbolAddress((void**)&slr,  g_slr);
    cudaGetSymbolAddress((void**)&gvb,  g_gv);
    cudaGetSymbolAddress((void**)&cw1,  g_cw1);

    __nv_bfloat16 *xn3, *kv3, *attn3, *fus3, *h23, *q3, *k3, *p3, *vt3;
    __nv_bfloat16 *wq3, *wk3, *wv3, *wo3, *wout3, *wfgvb3, *wt13, *cf3, *cw1t3, *tsc3;
    cudaGetSymbolAddress((void**)&xn3,    g3_xn);
    cudaGetSymbolAddress((void**)&kv3,    g3_kv);
    cudaGetSymbolAddress((void**)&attn3,  g3_attn);
    cudaGetSymbolAddress((void**)&fus3,   g3_fus);
    cudaGetSymbolAddress((void**)&h23,    g3_h2);
    cudaGetSymbolAddress((void**)&q3,     g3_q);
    cudaGetSymbolAddress((void**)&k3,     g3_k);
    cudaGetSymbolAddress((void**)&p3,     g3_p);
    cudaGetSymbolAddress((void**)&vt3,    g3_vt);
    cudaGetSymbolAddress((void**)&wq3,    g3_wq);
    cudaGetSymbolAddress((void**)&wk3,    g3_wk);
    cudaGetSymbolAddress((void**)&wv3,    g3_wv);
    cudaGetSymbolAddress((void**)&wo3,    g3_wo);
    cudaGetSymbolAddress((void**)&wout3,  g3_wout);
    cudaGetSymbolAddress((void**)&wfgvb3, g3_wfgvb);
    cudaGetSymbolAddress((void**)&wt13,   g3_wt1);
    cudaGetSymbolAddress((void**)&cf3,    g3_cf);
    cudaGetSymbolAddress((void**)&cw1t3,  g3_cw1t);
    cudaGetSymbolAddress((void**)&tsc3,   g3_tsc);

    dim3 tblk(32, 8);
    {
        T5Params tp;
        tp.W[0] = wq;    tp.Y[0] = wq3;
        tp.W[1] = wk;    tp.Y[1] = wk3;
        tp.W[2] = wv;    tp.Y[2] = wv3;
        tp.W[3] = wo;    tp.Y[3] = wo3;
        tp.W[4] = w_out; tp.Y[4] = wout3;
        transpose_split5_kernel<<<dim3(CD / 32, CD / 32, 5), tblk>>>(tp);
    }
    transpose_split_kernel<<<dim3((2 * CD) / 32, CD / 32), tblk>>>(
        w_fgv + (long long)CD * (2 * CD), wfgvb3, CD, 2 * CD);
    wt1_split_kernel<<<dim3((2 * CD) / 32, CD / 32), tblk>>>(w_fgv, wt13);

    rmsnorm_split_kernel<<<MT, 256>>>(x, w_in, xn, xn3, CD, 0);
    colmean_kernel<<<(CB * CD) / 256, 256>>>(xn, xm);
    mlp2_kernel<<<dim3(CDQ / 256, CB), 256>>>(xm, wc1, bc1, hs);
    coeff2_kernel<<<dim3(CNC / 256, CB), 256>>>(hs, wc2, bc2, coef);
    coeff3_kernel<<<dim3(8, 128), 256>>>(coef, w_nc, cf3);
    cheby3_kernel<<<MT, 256>>>(xn, coef, kv3, tsc3);

    // CW1 = coeff3 @ WT1 (batched over 8 heads)
    mm(cf3, wt13, cw1, 0, 0, 128, 2 * CD, 768, 768, 768, 2 * CD, 1.f,
       8, 1, (long long)128 * 768, 0, (long long)(2 * CD) * 768, 0,
       (long long)128 * (2 * CD), 0, 0, 0);
    cw1t_kernel<<<dim3((2 * CD) / 256, CB), 256>>>(cw1, cw1t3);

    // q/k projections -> head-split epilogues; v -> fp32
    mm(xn3, wq3, 0, 0, q3, MT, CD, 3 * CD, 3 * CD, 3 * CD, CD, 1.f,
       1, 1, 0, 0, 0, 0, 0, 0, 1, 0);
    mm(kv3, wk3, 0, 0, k3, MT, CD, 3 * CD, 3 * CD, 3 * CD, CD, 1.f,
       1, 1, 0, 0, 0, 0, 0, 0, 2, 0);
    mm(kv3, wv3, v, 0, 0, MT, CD, 3 * CD, 3 * CD, 3 * CD, CD, 1.f,
       1, 1, 0, 0, 0, 0, 0, 0, 0, 0);

    vtrans_split_kernel<<<dim3(CS / 32, CAHD / 32, CB * CAH), tblk>>>(v, vt3);

    // scores = q @ k^T / sqrt(hd) with causal tile skip
    mm(q3, k3, sc, 0, 0, CS, CS, 384, 3 * CD, 3 * CD, CS, 0.08838834764831845f,
       CB * CAH, CAH,
       (long long)CS * 3 * CD, 384,
       (long long)CS * 3 * CD, 384,
       (long long)CAH * CS * CS, (long long)CS * CS, 0, 1);

    softmax_split_kernel<<<CB * CAH * CS, 256>>>(sc, p3);

    // attn = P @ V -> attn3 split epilogue
    mm(p3, vt3, 0, 0, attn3, CS, CAHD, 3 * CS, 3 * CS, 3 * CS, CD, 1.f,
       CB * CAH, CAH,
       (long long)CAH * CS * 3 * CS, (long long)CS * 3 * CS,
       (long long)CAH * CAHD * 3 * CS, (long long)CAHD * 3 * CS,
       0, 0, 3, 0);

    // slr = attn @ wo
    mm(attn3, wo3, slr, 0, 0, MT, CD, 3 * CD, 3 * CD, 3 * CD, CD, 1.f,
       1, 1, 0, 0, 0, 0, 0, 0, 0, 0);

    // h2 = split(rmsnorm(slr, w_ns))
    rmsnorm_split_kernel<<<MT, 256>>>(slr, w_ns, 0, h23, CD, 0);

    // gv = (rs*T) @ CW1^T  (low-rank h1 path)
    mm(tsc3, cw1t3, gvb, 0, 0, CS, 2 * CD, 96, 96, 96, 2 * CD, 1.f,
       CB, 1, (long long)CS * 96, 0, (long long)(2 * CD) * 96, 0,
       (long long)CS * (2 * CD), 0, 0, 0);
    // gv += h2 @ wfgv_bottom
    mm(h23, wfgvb3, gvb, gvb, 0, MT, 2 * CD, 3 * CD, 3 * CD, 3 * CD, 2 * CD, 1.f,
       1, 1, 0, 0, 0, 0, 0, 0, 0, 0);

    fuse_split_kernel<<<MT, 256>>>(gvb, w_np, fus3);
    // out = x + fused @ w_out
    mm(fus3, wout3, out, x, 0, MT, CD, 3 * CD, 3 * CD, 3 * CD, CD, 1.f,
       1, 1, 0, 0, 0, 0, 0, 0, 0, 0);
}

// round 15
// speedup vs baseline: 1.0077x; 1.0073x over previous
#include <cuda_runtime.h>
#include <cuda_bf16.h>
#include <cstdint>
#include <math.h>

// ---------------- problem constants ----------------
#define CB   4
#define CS   512
#define CD   2048
#define CNH  8
#define CDEG 4
#define CHD  256
#define CAH  16
#define CAHD 128
#define CDQ  512
#define CNC  (CNH*CDEG*CHD)   // 8192
#define MT   (CB*CS)          // 2048 tokens

// ---------------- fp32 scratch ----------------
__device__ float g_xn   [MT*CD];
__device__ float g_xmean[CB*CD];
__device__ float g_hs   [CB*CDQ];
__device__ float g_coef [CB*CNC];
__device__ float g_v    [MT*CD];
__device__ float g_sc   [(size_t)CB*CAH*CS*CS];
__device__ float g_slr  [MT*CD];
__device__ float g_gv   [MT*2*CD];
__device__ float g_cw1  [(size_t)8*128*(2*CD)];

// ---------------- bf16 split scratch (3x K) ----------------
__device__ __align__(16) __nv_bfloat16 g3_xn   [MT*3*CD];
__device__ __align__(16) __nv_bfloat16 g3_kv   [MT*3*CD];
__device__ __align__(16) __nv_bfloat16 g3_attn [MT*3*CD];
__device__ __align__(16) __nv_bfloat16 g3_fus  [MT*3*CD];
__device__ __align__(16) __nv_bfloat16 g3_h2   [(size_t)MT*3*CD];
__device__ __align__(16) __nv_bfloat16 g3_q    [MT*3*CD];
__device__ __align__(16) __nv_bfloat16 g3_k    [MT*3*CD];
__device__ __align__(16) __nv_bfloat16 g3_p    [(size_t)CB*CAH*CS*3*CS];
__device__ __align__(16) __nv_bfloat16 g3_vt   [(size_t)CB*CAH*CAHD*3*CS];
__device__ __align__(16) __nv_bfloat16 g3_wq   [(size_t)CD*3*CD];
__device__ __align__(16) __nv_bfloat16 g3_wk   [(size_t)CD*3*CD];
__device__ __align__(16) __nv_bfloat16 g3_wv   [(size_t)CD*3*CD];
__device__ __align__(16) __nv_bfloat16 g3_wo   [(size_t)CD*3*CD];
__device__ __align__(16) __nv_bfloat16 g3_wout [(size_t)CD*3*CD];
__device__ __align__(16) __nv_bfloat16 g3_wfgvb[(size_t)(2*CD)*3*CD];
__device__ __align__(16) __nv_bfloat16 g3_wt1  [(size_t)8*(2*CD)*768];
__device__ __align__(16) __nv_bfloat16 g3_cf   [(size_t)8*128*768];
__device__ __align__(16) __nv_bfloat16 g3_cw1t [(size_t)CB*(2*CD)*96];
__device__ __align__(16) __nv_bfloat16 g3_tsc  [(size_t)MT*96];

// ---------------- helpers ----------------
__device__ __forceinline__ uint32_t smem_u32(const void* p) {
    uint32_t a;
    asm("{ .reg .u64 t; cvta.to.shared.u64 t, %1; cvt.u32.u64 %0, t; }" : "=r"(a) : "l"(p));
    return a;
}
__device__ __forceinline__ void cp16(uint32_t dst, const void* src) {
    asm volatile("cp.async.cg.shared.global [%0], [%1], 16;" :: "r"(dst), "l"(src) : "memory");
}
__device__ __forceinline__ void cp_commit() { asm volatile("cp.async.commit_group;" ::: "memory"); }

__device__ __forceinline__ void ldm_x4(uint32_t addr, uint32_t& r0, uint32_t& r1,
                                       uint32_t& r2, uint32_t& r3) {
    asm volatile("ldmatrix.sync.aligned.m8n8.x4.shared.b16 {%0,%1,%2,%3}, [%4];"
                 : "=r"(r0), "=r"(r1), "=r"(r2), "=r"(r3) : "r"(addr));
}
__device__ __forceinline__ void mma16816(float* c, const uint32_t* a, const uint32_t* b) {
    asm volatile("mma.sync.aligned.m16n8k16.row.col.f32.bf16.bf16.f32 "
                 "{%0,%1,%2,%3}, {%4,%5,%6,%7}, {%8,%9}, {%0,%1,%2,%3};"
                 : "+f"(c[0]), "+f"(c[1]), "+f"(c[2]), "+f"(c[3])
                 : "r"(a[0]), "r"(a[1]), "r"(a[2]), "r"(a[3]), "r"(b[0]), "r"(b[1]));
}

__device__ __forceinline__ void split2(float a, __nv_bfloat16& hi, __nv_bfloat16& lo) {
    hi = __float2bfloat16(a);
    lo = __float2bfloat16(a - __bfloat162float(hi));
}

// ---------------- reductions (blockDim == 256) ----------------
__device__ __forceinline__ float warpSum(float v) {
    #pragma unroll
    for (int o = 16; o > 0; o >>= 1) v += __shfl_xor_sync(0xffffffffu, v, o);
    return v;
}
__device__ __forceinline__ float warpMax(float v) {
    #pragma unroll
    for (int o = 16; o > 0; o >>= 1) v = fmaxf(v, __shfl_xor_sync(0xffffffffu, v, o));
    return v;
}
__device__ __forceinline__ float blockSum(float v) {
    __shared__ float sh[8];
    v = warpSum(v);
    __syncthreads();
    if ((threadIdx.x & 31) == 0) sh[threadIdx.x >> 5] = v;
    __syncthreads();
    float r = sh[0];
    #pragma unroll
    for (int i = 1; i < 8; i++) r += sh[i];
    return r;
}
__device__ __forceinline__ float blockMax(float v) {
    __shared__ float shm[8];
    v = warpMax(v);
    __syncthreads();
    if ((threadIdx.x & 31) == 0) shm[threadIdx.x >> 5] = v;
    __syncthreads();
    float r = shm[0];
    #pragma unroll
    for (int i = 1; i < 8; i++) r = fmaxf(r, shm[i]);
    return r;
}

// =================== persistent HMMA bf16 GEMM (R6, FROZEN) ================
#define ROWB 80
#define TILEB (128*ROWB)
#define STGB  (2*TILEB)
#define NSTG  4
#define MM_SMEM (NSTG*STGB)  // 81920

struct MMParams {
    const __nv_bfloat16* A;
    const __nv_bfloat16* B;
    float* C;
    const float* Add;
    __nv_bfloat16* S3;
    int lda, ldb, ldc, K3;
    float alpha;
    int bdiv;
    long long sAo, sAi, sBo, sBi, sCo, sCi;
    int tilesM, tilesN, total;
    int mode;        // 0 fp32 C(+Add); 1 q3 split; 2 k3 split; 3 attn3 split
    int causal;
};

__global__ void __launch_bounds__(256, 2)
mm_bf16_kernel(MMParams p) {
    extern __shared__ __align__(128) char sm[];

    const int tid  = threadIdx.x, lane = tid & 31, wid = tid >> 5;
    const int wm   = wid >> 2, wn = wid & 3;
    const uint32_t sbase = smem_u32(sm);
    const int lrow = tid >> 1;
    const int lch  = (tid & 1) * 2;
    const uint32_t sAw = sbase + lrow * ROWB + lch * 16;
    const uint32_t sBw = sAw + TILEB;
    const int lr15 = lane & 15, lhi = lane >> 4;
    const uint32_t aoff = (uint32_t)((wm * 64 + lr15) * ROWB + lhi * 16);
    const uint32_t boff = (uint32_t)((wn * 32 + lr15) * ROWB + lhi * 16) + TILEB;
    const int tilesMN = p.tilesM * p.tilesN;
    const int NK = p.K3 / 32;

    for (int t = blockIdx.x; t < p.total; t += gridDim.x) {
        int z  = t / tilesMN;
        int r  = t - z * tilesMN;
        int ty = r / p.tilesN, tx = r - ty * p.tilesN;
        if (p.causal && tx > ty) continue;
        int zo = z / p.bdiv, zi = z - zo * p.bdiv;

        const __nv_bfloat16* Agb = p.A + zo * p.sAo + zi * p.sAi
                                   + (long long)(ty * 128 + lrow) * p.lda + lch * 8;
        const __nv_bfloat16* Bgb = p.B + zo * p.sBo + zi * p.sBi
                                   + (long long)(tx * 128 + lrow) * p.ldb + lch * 8;

        float acc[4][4][4];
        #pragma unroll
        for (int i = 0; i < 4; i++)
            #pragma unroll
            for (int j = 0; j < 4; j++)
                #pragma unroll
                for (int e = 0; e < 4; e++) acc[i][j][e] = 0.f;

        #pragma unroll
        for (int s = 0; s < 3; s++) {
            uint32_t o = (uint32_t)s * STGB;
            const __nv_bfloat16* Ag = Agb + s * 32;
            const __nv_bfloat16* Bg = Bgb + s * 32;
            cp16(sAw + o,      Ag);
            cp16(sAw + o + 16, Ag + 8);
            cp16(sBw + o,      Bg);
            cp16(sBw + o + 16, Bg + 8);
            cp_commit();
        }

        for (int kc = 0; kc < NK; kc++) {
            asm volatile("cp.async.wait_group 2;" ::: "memory");
            __syncthreads();
            if (kc + 3 < NK) {
                uint32_t o = (uint32_t)((kc + 3) & 3) * STGB;
                const __nv_bfloat16* Ag = Agb + (kc + 3) * 32;
                const __nv_bfloat16* Bg = Bgb + (kc + 3) * 32;
                cp16(sAw + o,      Ag);
                cp16(sAw + o + 16, Ag + 8);
                cp16(sBw + o,      Bg);
                cp16(sBw + o + 16, Bg + 8);
            }
            cp_commit();

            uint32_t sA = sbase + (uint32_t)(kc & 3) * STGB + aoff;
            uint32_t sB = sbase + (uint32_t)(kc & 3) * STGB + boff;
            #pragma unroll
            for (int ks = 0; ks < 2; ks++) {
                uint32_t a[4][4];
                #pragma unroll
                for (int mt = 0; mt < 4; mt++)
                    ldm_x4(sA + mt * (16 * ROWB) + ks * 32, a[mt][0], a[mt][1], a[mt][2], a[mt][3]);
                uint32_t b[4][2];
                #pragma unroll
                for (int bt = 0; bt < 2; bt++) {
                    uint32_t r0, r1, r2, r3;
                    ldm_x4(sB + bt * (16 * ROWB) + ks * 32, r0, r1, r2, r3);
                    b[bt * 2 + 0][0] = r0; b[bt * 2 + 0][1] = r2;
                    b[bt * 2 + 1][0] = r1; b[bt * 2 + 1][1] = r3;
                }
                #pragma unroll
                for (int mt = 0; mt < 4; mt++)
                    #pragma unroll
                    for (int nt = 0; nt < 4; nt++)
                        mma16816(acc[mt][nt], a[mt], b[nt]);
            }
        }
        __syncthreads();

        const int row0 = ty * 128, col0 = tx * 128;
        const int erow = wm * 64 + (lane >> 2);
        const int ecol = wn * 32 + (lane & 3) * 2;

        if (p.mode == 0) {
            long long coff = zo * p.sCo + zi * p.sCi;
            #pragma unroll
            for (int mt = 0; mt < 4; mt++)
                #pragma unroll
                for (int half = 0; half < 2; half++) {
                    int gr = row0 + erow + mt * 16 + half * 8;
                    long long rb = (long long)gr * p.ldc + col0 + ecol + coff;
                    #pragma unroll
                    for (int nt = 0; nt < 4; nt++) {
                        float2 v;
                        v.x = acc[mt][nt][half * 2 + 0] * p.alpha;
                        v.y = acc[mt][nt][half * 2 + 1] * p.alpha;
                        if (p.Add) {
                            float2 ad = *(const float2*)(p.Add + rb + nt * 8);
                            v.x += ad.x; v.y += ad.y;
                        }
                        *(float2*)(p.C + rb + nt * 8) = v;
                    }
                }
        } else if (p.mode == 3) {
            int b = z >> 4, h = z & 15;
            #pragma unroll
            for (int mt = 0; mt < 4; mt++)
                #pragma unroll
                for (int half = 0; half < 2; half++) {
                    int gr = row0 + erow + mt * 16 + half * 8;
                    long long base = ((long long)(b * CS + gr)) * (3LL * CD)
                                     + h * CAHD + col0 + ecol;
                    #pragma unroll
                    for (int nt = 0; nt < 4; nt++) {
                        float v0 = acc[mt][nt][half * 2 + 0];
                        float v1 = acc[mt][nt][half * 2 + 1];
                        __nv_bfloat16 h0, l0, h1, l1;
                        split2(v0, h0, l0); split2(v1, h1, l1);
                        __nv_bfloat162 hh = __nv_bfloat162(h0, h1);
                        __nv_bfloat162 ll = __nv_bfloat162(l0, l1);
                        __nv_bfloat16* d0 = (__nv_bfloat16*)(p.S3 + base + nt * 8);
                        *(__nv_bfloat162*)(d0)          = hh;
                        *(__nv_bfloat162*)(d0 + CD)     = hh;
                        *(__nv_bfloat162*)(d0 + 2 * CD) = ll;
                    }
                }
        } else {
            #pragma unroll
            for (int mt = 0; mt < 4; mt++)
                #pragma unroll
                for (int half = 0; half < 2; half++) {
                    int gr = row0 + erow + mt * 16 + half * 8;
                    long long rowb = (long long)gr * (3LL * CD);
                    #pragma unroll
                    for (int nt = 0; nt < 4; nt++) {
                        int n = col0 + ecol + nt * 8;
                        int hh_ = n >> 7, d = n & 127;
                        long long base = rowb + hh_ * 384 + d;
                        float v0 = acc[mt][nt][half * 2 + 0];
                        float v1 = acc[mt][nt][half * 2 + 1];
                        __nv_bfloat16 h0, l0, h1, l1;
                        split2(v0, h0, l0); split2(v1, h1, l1);
                        __nv_bfloat162 hv = __nv_bfloat162(h0, h1);
                        __nv_bfloat162 lv = __nv_bfloat162(l0, l1);
                        __nv_bfloat16* dp = p.S3 + base;
                        *(__nv_bfloat162*)(dp)       = hv;
                        *(__nv_bfloat162*)(dp + 128) = (p.mode == 1) ? hv : lv;
                        *(__nv_bfloat162*)(dp + 256) = (p.mode == 1) ? lv : hv;
                    }
                }
        }
    }
}

// =================== elementwise / prep kernels ===================

// rmsnorm -> fp32 out (optional) + A-side split (hi,hi,lo); vectorized pairs
__global__ void rmsnorm_split_kernel(const float* __restrict__ in, const float* __restrict__ w,
                                     float* __restrict__ outf, __nv_bfloat16* __restrict__ out3,
                                     int Ktot, int colofs) {
    long long row = blockIdx.x;
    const float2* ip2 = (const float2*)(in + row * CD);
    const float2* w2  = (const float2*)w;
    float2 vals[4];
    float ss = 0.f;
    #pragma unroll
    for (int ii = 0; ii < 4; ii++) {
        int p = threadIdx.x + ii * 256;
        float2 u = ip2[p];
        vals[ii] = u;
        ss = fmaf(u.x, u.x, ss);
        ss = fmaf(u.y, u.y, ss);
    }
    ss = blockSum(ss);
    float rs = rsqrtf(ss * (1.f / CD) + 1e-6f);
    long long b3 = row * 3LL * Ktot + colofs;
    #pragma unroll
    for (int ii = 0; ii < 4; ii++) {
        int p = threadIdx.x + ii * 256;
        float2 wv = w2[p];
        float ux = vals[ii].x * rs * wv.x;
        float uy = vals[ii].y * rs * wv.y;
        if (outf) ((float2*)(outf + row * CD))[p] = make_float2(ux, uy);
        __nv_bfloat16 hx, lx, hy, ly;
        split2(ux, hx, lx); split2(uy, hy, ly);
        __nv_bfloat162 hv(hx, hy), lv(lx, ly);
        __nv_bfloat16* dp = out3 + b3 + 2 * p;
        *(__nv_bfloat162*)(dp)            = hv;
        *(__nv_bfloat162*)(dp + Ktot)     = hv;
        *(__nv_bfloat162*)(dp + 2 * Ktot) = lv;
    }
}

__global__ void colmean_kernel(const float* __restrict__ xn, float* __restrict__ xm) {
    int idx = blockIdx.x * blockDim.x + threadIdx.x;
    int b = idx / CD, d = idx % CD;
    float s = 0.f;
    for (int t = 0; t < CS; t++) s += xn[((long long)b * CS + t) * CD + d];
    xm[idx] = s * (1.f / CS);
}

__global__ void mlp2_kernel(const float* __restrict__ xm, const float* __restrict__ wc1,
                            const float* __restrict__ bc1, float* __restrict__ h) {
    int b = blockIdx.y, c = blockIdx.x * 256 + threadIdx.x;
    float s = 0.f;
    for (int k = 0; k < CD; k++) s = fmaf(xm[b * CD + k], wc1[(long long)k * CDQ + c], s);
    s += bc1[c];
    h[b * CDQ + c] = s / (1.f + expf(-s));
}

__global__ void coeff2_kernel(const float* __restrict__ h, const float* __restrict__ wc2,
                              const float* __restrict__ bc2, float* __restrict__ coef) {
    int b = blockIdx.y, c = blockIdx.x * 256 + threadIdx.x;
    float s = 0.f;
    for (int k = 0; k < CDQ; k++) s = fmaf(h[b * CDQ + k], wc2[(long long)k * CNC + c], s);
    s += bc2[c];
    int kdeg = (c / CHD) % CDEG;
    coef[(long long)b * CNC + c] = s * (0.1f / (float)(kdeg + 1));
}

__global__ void coeff3_kernel(const float* __restrict__ coef, const float* __restrict__ wnc,
                              __nv_bfloat16* __restrict__ cf3) {
    int h = blockIdx.x, r = blockIdx.y, i = threadIdx.x;
    float val = 0.f;
    if (r < 16) {
        int b = r >> 2, kd = r & 3;
        val = coef[(long long)b * CNC + (h * 4 + kd) * CHD + i] * wnc[h * CHD + i];
    }
    __nv_bfloat16 hi, lo; split2(val, hi, lo);
    long long base = ((long long)h * 128 + r) * 768;
    cf3[base + i] = hi;
    cf3[base + 256 + i] = hi;
    cf3[base + 512 + i] = lo;
}

// cheby: kv split vectorized (pairs); tsc3 unchanged
__global__ void cheby3_kernel(const float* __restrict__ xn, const float* __restrict__ coef,
                              __nv_bfloat16* __restrict__ kv3, __nv_bfloat16* __restrict__ tsc3) {
    long long bs = blockIdx.x;
    int b = (int)(bs / CS);
    int w = threadIdx.x >> 5, lane = threadIdx.x & 31;
    const float2* u2 = (const float2*)(xn + bs * CD + w * CHD);
    float s = 0.f;
    #pragma unroll
    for (int pass = 0; pass < 4; pass++) {
        float2 u = u2[lane + pass * 32];
        s += u.x + u.y;
    }
    s = warpSum(s);
    float z = tanhf(s * (1.f / CHD));
    float T1 = z, T2 = 2.f * z * z - 1.f, T3 = 2.f * z * T2 - T1;
    const float2* cp2 = (const float2*)(coef + (((long long)b * CNH + w) * CDEG) * CHD);
    long long b3 = bs * (3LL * CD) + w * CHD;
    float ssloc = 0.f;
    #pragma unroll
    for (int pass = 0; pass < 4; pass++) {
        int p = lane + pass * 32;
        float2 c0 = cp2[p];
        float2 c1 = cp2[128 + p];
        float2 c2 = cp2[256 + p];
        float2 c3 = cp2[384 + p];
        float2 u  = u2[p];
        float ox = c0.x + T1 * c1.x + T2 * c2.x + T3 * c3.x;
        float oy = c0.y + T1 * c1.y + T2 * c2.y + T3 * c3.y;
        ssloc = fmaf(ox, ox, ssloc);
        ssloc = fmaf(oy, oy, ssloc);
        float vx = u.x + ox, vy = u.y + oy;
        __nv_bfloat16 hx, lx, hy, ly;
        split2(vx, hx, lx); split2(vy, hy, ly);
        __nv_bfloat162 hv(hx, hy), lv(lx, ly);
        __nv_bfloat16* dp = kv3 + b3 + 2 * p;
        *(__nv_bfloat162*)(dp)          = hv;
        *(__nv_bfloat162*)(dp + CD)     = hv;
        *(__nv_bfloat162*)(dp + 2 * CD) = lv;
    }
    float ss = blockSum(ssloc);
    float rs = rsqrtf(ss * (1.f / CD) + 1e-6f);
    if (lane < 4) {
        float tv = (lane == 0) ? 1.f : (lane == 1) ? T1 : (lane == 2) ? T2 : T3;
        tv *= rs;
        __nv_bfloat16 hi, lo; split2(tv, hi, lo);
        long long base = bs * 96 + w * 4 + lane;
        tsc3[base]      = hi;
        tsc3[base + 32] = hi;
        tsc3[base + 64] = lo;
    }
}

// batched 2048x2048 transpose + B-side split for 5 weights; 64(k)x32(n) tiles,
// bf162-pair stores (128B/warp per slice)
struct T5Params {
    const float* W[5];
    __nv_bfloat16* Y[5];
};
__global__ void transpose_split5_kernel(T5Params p) {
    __shared__ float t[64][33];
    const float* W = p.W[blockIdx.z];
    __nv_bfloat16* Y = p.Y[blockIdx.z];
    int k0 = blockIdx.y * 64, n0 = blockIdx.x * 32;
    int tx = threadIdx.x, ty = threadIdx.y;      // 32 x 8
    #pragma unroll
    for (int i = 0; i < 8; i++) {
        int r = ty + i * 8;
        t[r][tx] = W[(long long)(k0 + r) * CD + n0 + tx];
    }
    __syncthreads();
    #pragma unroll
    for (int i = 0; i < 4; i++) {
        int c = ty + i * 8;                       // n - n0
        int n = n0 + c;
        float a0 = t[2 * tx][c];
        float a1 = t[2 * tx + 1][c];
        __nv_bfloat16 h0, l0, h1, l1;
        split2(a0, h0, l0); split2(a1, h1, l1);
        __nv_bfloat162 hv(h0, h1), lv(l0, l1);
        long long base = (long long)n * 3 * CD + k0 + 2 * tx;
        *(__nv_bfloat162*)(Y + base)          = hv;
        *(__nv_bfloat162*)(Y + base + CD)     = lv;
        *(__nv_bfloat162*)(Y + base + 2 * CD) = hv;
    }
}

// general transpose + B-side split (fgv bottom): 64(k)x32(n) tiles
__global__ void transpose_split_kernel(const float* __restrict__ W, __nv_bfloat16* __restrict__ Y,
                                       int K, int N) {
    __shared__ float t[64][33];
    int k0 = blockIdx.y * 64, n0 = blockIdx.x * 32;
    int tx = threadIdx.x, ty = threadIdx.y;
    #pragma unroll
    for (int i = 0; i < 8; i++) {
        int r = ty + i * 8;
        t[r][tx] = W[(long long)(k0 + r) * N + n0 + tx];
    }
    __syncthreads();
    #pragma unroll
    for (int i = 0; i < 4; i++) {
        int c = ty + i * 8;
        int n = n0 + c;
        float a0 = t[2 * tx][c];
        float a1 = t[2 * tx + 1][c];
        __nv_bfloat16 h0, l0, h1, l1;
        split2(a0, h0, l0); split2(a1, h1, l1);
        __nv_bfloat162 hv(h0, h1), lv(l0, l1);
        long long base = (long long)n * 3 * K + k0 + 2 * tx;
        *(__nv_bfloat162*)(Y + base)         = hv;
        *(__nv_bfloat162*)(Y + base + K)     = lv;
        *(__nv_bfloat162*)(Y + base + 2 * K) = hv;
    }
}

// wfgv TOP half -> per-head transposed split; 64(k)x32(n) tiles
__global__ void wt1_split_kernel(const float* __restrict__ W, __nv_bfloat16* __restrict__ Y) {
    __shared__ float t[64][33];
    int k0 = blockIdx.y * 64, n0 = blockIdx.x * 32;
    int tx = threadIdx.x, ty = threadIdx.y;
    #pragma unroll
    for (int i = 0; i < 8; i++) {
        int r = ty + i * 8;
        t[r][tx] = W[(long long)(k0 + r) * (2 * CD) + n0 + tx];
    }
    __syncthreads();
    int h = k0 >> 8;                      // 64-block stays within one 256-head block
    int d0 = (k0 & 255) + 2 * tx;
    #pragma unroll
    for (int i = 0; i < 4; i++) {
        int c = ty + i * 8;
        int n = n0 + c;
        float a0 = t[2 * tx][c];
        float a1 = t[2 * tx + 1][c];
        __nv_bfloat16 h0, l0, h1, l1;
        split2(a0, h0, l0); split2(a1, h1, l1);
        __nv_bfloat162 hv(h0, h1), lv(l0, l1);
        long long base = ((long long)h * (2 * CD) + n) * 768 + d0;
        *(__nv_bfloat162*)(Y + base)       = hv;
        *(__nv_bfloat162*)(Y + base + 256) = lv;
        *(__nv_bfloat162*)(Y + base + 512) = hv;
    }
}

__global__ void cw1t_kernel(const float* __restrict__ CW1, __nv_bfloat16* __restrict__ Y) {
    int n = blockIdx.x * 256 + threadIdx.x;
    int b = blockIdx.y;
    long long obase = ((long long)b * (2 * CD) + n) * 96;
    #pragma unroll
    for (int j = 0; j < 32; j++) {
        int h = j >> 2, kd = j & 3;
        float v = CW1[(((long long)h * 128) + b * 4 + kd) * (2 * CD) + n];
        __nv_bfloat16 hi, lo; split2(v, hi, lo);
        Y[obase + j] = hi;
        Y[obase + 32 + j] = lo;
        Y[obase + 64 + j] = hi;
    }
}

// per-head V transpose + B-side split; 64(k over seq)x32(n over headdim) tiles
__global__ void vtrans_split_kernel(const float* __restrict__ v, __nv_bfloat16* __restrict__ vt3) {
    __shared__ float t[64][33];
    int bh = blockIdx.z, b = bh >> 4, h = bh & 15;
    int k0 = blockIdx.x * 64, n0 = blockIdx.y * 32;
    int tx = threadIdx.x, ty = threadIdx.y;
    #pragma unroll
    for (int i = 0; i < 8; i++) {
        int r = ty + i * 8;
        t[r][tx] = v[((long long)(b * CS + k0 + r)) * CD + h * CAHD + n0 + tx];
    }
    __syncthreads();
    #pragma unroll
    for (int i = 0; i < 4; i++) {
        int c = ty + i * 8;
        int n = n0 + c;
        float a0 = t[2 * tx][c];
        float a1 = t[2 * tx + 1][c];
        __nv_bfloat16 h0, l0, h1, l1;
        split2(a0, h0, l0); split2(a1, h1, l1);
        __nv_bfloat162 hv(h0, h1), lv(l0, l1);
        long long base = ((long long)bh * CAHD + n) * (3 * CS) + k0 + 2 * tx;
        *(__nv_bfloat162*)(vt3 + base)          = hv;
        *(__nv_bfloat162*)(vt3 + base + CS)     = lv;
        *(__nv_bfloat162*)(vt3 + base + 2 * CS) = hv;
    }
}

// fused = rmsnorm(silu(g)*v, w_np) -> A-side split; vectorized pairs
__global__ void fuse_split_kernel(const float* __restrict__ gv, const float* __restrict__ wnp,
                                  __nv_bfloat16* __restrict__ out3) {
    long long row = blockIdx.x;
    const float2* gp2 = (const float2*)(gv + row * (2 * CD));
    const float2* w2  = (const float2*)wnp;
    float2 t[4];
    float ss = 0.f;
    #pragma unroll
    for (int ii = 0; ii < 4; ii++) {
        int p = threadIdx.x + ii * 256;
        float2 g = gp2[p];
        float2 v = gp2[CD / 2 + p];
        float ux = g.x / (1.f + expf(-g.x)) * v.x;
        float uy = g.y / (1.f + expf(-g.y)) * v.y;
        t[ii] = make_float2(ux, uy);
        ss = fmaf(ux, ux, ss);
        ss = fmaf(uy, uy, ss);
    }
    ss = blockSum(ss);
    float rs = rsqrtf(ss * (1.f / CD) + 1e-6f);
    long long b3 = row * (3LL * CD);
    #pragma unroll
    for (int ii = 0; ii < 4; ii++) {
        int p = threadIdx.x + ii * 256;
        float2 wv = w2[p];
        float ux = t[ii].x * rs * wv.x;
        float uy = t[ii].y * rs * wv.y;
        __nv_bfloat16 hx, lx, hy, ly;
        split2(ux, hx, lx); split2(uy, hy, ly);
        __nv_bfloat162 hv(hx, hy), lv(lx, ly);
        __nv_bfloat16* dp = out3 + b3 + 2 * p;
        *(__nv_bfloat162*)(dp)          = hv;
        *(__nv_bfloat162*)(dp + CD)     = hv;
        *(__nv_bfloat162*)(dp + 2 * CD) = lv;
    }
}

// causal softmax over 512-wide rows; vectorized pairs; split probs
__global__ void softmax_split_kernel(const float* __restrict__ sc, __nv_bfloat16* __restrict__ p3) {
    long long row = blockIdx.x;
    int i = (int)(row % CS);
    const float2* sp2 = (const float2*)(sc + row * CS);
    int j2 = threadIdx.x;
    int c0 = 2 * j2, c1 = 2 * j2 + 1;
    float2 sv = make_float2(0.f, 0.f);
    float m = -1e30f;
    if (c0 <= i) {
        sv = sp2[j2];
        m = fmaxf(m, sv.x);
        if (c1 <= i) m = fmaxf(m, sv.y);
    }
    m = blockMax(m);
    float ex = (c0 <= i) ? expf(sv.x - m) : 0.f;
    float ey = (c1 <= i) ? expf(sv.y - m) : 0.f;
    float s = blockSum(ex + ey);
    float inv = 1.f / s;
    float ux = ex * inv, uy = ey * inv;
    __nv_bfloat16 hx, lx, hy, ly;
    split2(ux, hx, lx); split2(uy, hy, ly);
    __nv_bfloat162 hv(hx, hy), lv(lx, ly);
    long long b3 = row * (3LL * CS);
    __nv_bfloat16* dp = p3 + b3 + c0;
    *(__nv_bfloat162*)(dp)          = hv;
    *(__nv_bfloat162*)(dp + CS)     = hv;
    *(__nv_bfloat162*)(dp + 2 * CS) = lv;
}

// ---------------- host ----------------
static int g_grid = 296;

static void mm(const __nv_bfloat16* A, const __nv_bfloat16* B, float* C, const float* Add,
               __nv_bfloat16* S3, int M, int N, int K3, int lda, int ldb, int ldc, float alpha,
               int bz, int bdiv, long long sAo, long long sAi, long long sBo, long long sBi,
               long long sCo, long long sCi, int mode, int causal) {
    MMParams p;
    p.A = A; p.B = B; p.C = C; p.Add = Add; p.S3 = S3;
    p.lda = lda; p.ldb = ldb; p.ldc = ldc; p.K3 = K3; p.alpha = alpha;
    p.bdiv = bdiv; p.sAo = sAo; p.sAi = sAi; p.sBo = sBo; p.sBi = sBi;
    p.sCo = sCo; p.sCi = sCi;
    p.tilesM = M / 128; p.tilesN = N / 128;
    p.total = bz * p.tilesM * p.tilesN;
    p.mode = mode; p.causal = causal;
    int grid = g_grid < p.total ? g_grid : p.total;
    mm_bf16_kernel<<<grid, 256, MM_SMEM>>>(p);
}

extern "C" void kernel_launch(void* const* d_in, const int* in_sizes, int n_in,
                              void* d_out, int out_size) {
    const float* x     = (const float*)d_in[0];
    const float* w_in  = (const float*)d_in[1];
    const float* wc1   = (const float*)d_in[6];
    const float* bc1   = (const float*)d_in[7];
    const float* wc2   = (const float*)d_in[8];
    const float* bc2   = (const float*)d_in[9];
    const float* wq    = (const float*)d_in[10];
    const float* wk    = (const float*)d_in[11];
    const float* wv    = (const float*)d_in[12];
    const float* wo    = (const float*)d_in[13];
    const float* w_nc  = (const float*)d_in[14];
    const float* w_ns  = (const float*)d_in[15];
    const float* w_fgv = (const float*)d_in[16];
    const float* w_np  = (const float*)d_in[17];
    const float* w_out = (const float*)d_in[18];
    float* out = (float*)d_out;

    int smc = 148;
    cudaDeviceGetAttribute(&smc, cudaDevAttrMultiProcessorCount, 0);
    g_grid = 2 * smc;

    cudaFuncSetAttribute(mm_bf16_kernel, cudaFuncAttributeMaxDynamicSharedMemorySize, MM_SMEM);

    float *xn, *xm, *hs, *coef, *v, *sc, *slr, *gvb, *cw1;
    cudaGetSymbolAddress((void**)&xn,   g_xn);
    cudaGetSymbolAddress((void**)&xm,   g_xmean);
    cudaGetSymbolAddress((void**)&hs,   g_hs);
    cudaGetSymbolAddress((void**)&coef, g_coef);
    cudaGetSymbolAddress((void**)&v,    g_v);
    cudaGetSymbolAddress((void**)&sc,   g_sc);
    cudaGetSymbolAddress((void**)&slr,  g_slr);
    cudaGetSymbolAddress((void**)&gvb,  g_gv);
    cudaGetSymbolAddress((void**)&cw1,  g_cw1);

    __nv_bfloat16 *xn3, *kv3, *attn3, *fus3, *h23, *q3, *k3, *p3, *vt3;
    __nv_bfloat16 *wq3, *wk3, *wv3, *wo3, *wout3, *wfgvb3, *wt13, *cf3, *cw1t3, *tsc3;
    cudaGetSymbolAddress((void**)&xn3,    g3_xn);
    cudaGetSymbolAddress((void**)&kv3,    g3_kv);
    cudaGetSymbolAddress((void**)&attn3,  g3_attn);
    cudaGetSymbolAddress((void**)&fus3,   g3_fus);
    cudaGetSymbolAddress((void**)&h23,    g3_h2);
    cudaGetSymbolAddress((void**)&q3,     g3_q);
    cudaGetSymbolAddress((void**)&k3,     g3_k);
    cudaGetSymbolAddress((void**)&p3,     g3_p);
    cudaGetSymbolAddress((void**)&vt3,    g3_vt);
    cudaGetSymbolAddress((void**)&wq3,    g3_wq);
    cudaGetSymbolAddress((void**)&wk3,    g3_wk);
    cudaGetSymbolAddress((void**)&wv3,    g3_wv);
    cudaGetSymbolAddress((void**)&wo3,    g3_wo);
    cudaGetSymbolAddress((void**)&wout3,  g3_wout);
    cudaGetSymbolAddress((void**)&wfgvb3, g3_wfgvb);
    cudaGetSymbolAddress((void**)&wt13,   g3_wt1);
    cudaGetSymbolAddress((void**)&cf3,    g3_cf);
    cudaGetSymbolAddress((void**)&cw1t3,  g3_cw1t);
    cudaGetSymbolAddress((void**)&tsc3,   g3_tsc);

    dim3 tblk(32, 8);
    {
        T5Params tp;
        tp.W[0] = wq;    tp.Y[0] = wq3;
        tp.W[1] = wk;    tp.Y[1] = wk3;
        tp.W[2] = wv;    tp.Y[2] = wv3;
        tp.W[3] = wo;    tp.Y[3] = wo3;
        tp.W[4] = w_out; tp.Y[4] = wout3;
        transpose_split5_kernel<<<dim3(CD / 32, CD / 64, 5), tblk>>>(tp);
    }
    transpose_split_kernel<<<dim3((2 * CD) / 32, CD / 64), tblk>>>(
        w_fgv + (long long)CD * (2 * CD), wfgvb3, CD, 2 * CD);
    wt1_split_kernel<<<dim3((2 * CD) / 32, CD / 64), tblk>>>(w_fgv, wt13);

    rmsnorm_split_kernel<<<MT, 256>>>(x, w_in, xn, xn3, CD, 0);
    colmean_kernel<<<(CB * CD) / 256, 256>>>(xn, xm);
    mlp2_kernel<<<dim3(CDQ / 256, CB), 256>>>(xm, wc1, bc1, hs);
    coeff2_kernel<<<dim3(CNC / 256, CB), 256>>>(hs, wc2, bc2, coef);
    coeff3_kernel<<<dim3(8, 128), 256>>>(coef, w_nc, cf3);
    cheby3_kernel<<<MT, 256>>>(xn, coef, kv3, tsc3);

    // CW1 = coeff3 @ WT1 (batched over 8 heads)
    mm(cf3, wt13, cw1, 0, 0, 128, 2 * CD, 768, 768, 768, 2 * CD, 1.f,
       8, 1, (long long)128 * 768, 0, (long long)(2 * CD) * 768, 0,
       (long long)128 * (2 * CD), 0, 0, 0);
    cw1t_kernel<<<dim3((2 * CD) / 256, CB), 256>>>(cw1, cw1t3);

    // q/k projections -> head-split epilogues; v -> fp32
    mm(xn3, wq3, 0, 0, q3, MT, CD, 3 * CD, 3 * CD, 3 * CD, CD, 1.f,
       1, 1, 0, 0, 0, 0, 0, 0, 1, 0);
    mm(kv3, wk3, 0, 0, k3, MT, CD, 3 * CD, 3 * CD, 3 * CD, CD, 1.f,
       1, 1, 0, 0, 0, 0, 0, 0, 2, 0);
    mm(kv3, wv3, v, 0, 0, MT, CD, 3 * CD, 3 * CD, 3 * CD, CD, 1.f,
       1, 1, 0, 0, 0, 0, 0, 0, 0, 0);

    vtrans_split_kernel<<<dim3(CS / 64, CAHD / 32, CB * CAH), tblk>>>(v, vt3);

    // scores = q @ k^T / sqrt(hd) with causal tile skip
    mm(q3, k3, sc, 0, 0, CS, CS, 384, 3 * CD, 3 * CD, CS, 0.08838834764831845f,
       CB * CAH, CAH,
       (long long)CS * 3 * CD, 384,
       (long long)CS * 3 * CD, 384,
       (long long)CAH * CS * CS, (long long)CS * CS, 0, 1);

    softmax_split_kernel<<<CB * CAH * CS, 256>>>(sc, p3);

    // attn = P @ V -> attn3 split epilogue
    mm(p3, vt3, 0, 0, attn3, CS, CAHD, 3 * CS, 3 * CS, 3 * CS, CD, 1.f,
       CB * CAH, CAH,
       (long long)CAH * CS * 3 * CS, (long long)CS * 3 * CS,
       (long long)CAH * CAHD * 3 * CS, (long long)CAHD * 3 * CS,
       0, 0, 3, 0);

    // slr = attn @ wo
    mm(attn3, wo3, slr, 0, 0, MT, CD, 3 * CD, 3 * CD, 3 * CD, CD, 1.f,
       1, 1, 0, 0, 0, 0, 0, 0, 0, 0);

    // h2 = split(rmsnorm(slr, w_ns))
    rmsnorm_split_kernel<<<MT, 256>>>(slr, w_ns, 0, h23, CD, 0);

    // gv = (rs*T) @ CW1^T  (low-rank h1 path)
    mm(tsc3, cw1t3, gvb, 0, 0, CS, 2 * CD, 96, 96, 96, 2 * CD, 1.f,
       CB, 1, (long long)CS * 96, 0, (long long)(2 * CD) * 96, 0,
       (long long)CS * (2 * CD), 0, 0, 0);
    // gv += h2 @ wfgv_bottom
    mm(h23, wfgvb3, gvb, gvb, 0, MT, 2 * CD, 3 * CD, 3 * CD, 3 * CD, 2 * CD, 1.f,
       1, 1, 0, 0, 0, 0, 0, 0, 0, 0);

    fuse_split_kernel<<<MT, 256>>>(gvb, w_np, fus3);
    // out = x + fused @ w_out
    mm(fus3, wout3, out, x, 0, MT, CD, 3 * CD, 3 * CD, 3 * CD, CD, 1.f,
       1, 1, 0, 0, 0, 0, 0, 0, 0, 0);
}

// round 16
// speedup vs baseline: 1.0090x; 1.0014x over previous
#include <cuda_runtime.h>
#include <cuda_bf16.h>
#include <cstdint>
#include <math.h>

// ---------------- problem constants ----------------
#define CB   4
#define CS   512
#define CD   2048
#define CNH  8
#define CDEG 4
#define CHD  256
#define CAH  16
#define CAHD 128
#define CDQ  512
#define CNC  (CNH*CDEG*CHD)   // 8192
#define MT   (CB*CS)          // 2048 tokens

// ---------------- fp32 scratch ----------------
__device__ float g_xn   [MT*CD];
__device__ float g_xmean[CB*CD];
__device__ float g_hs   [CB*CDQ];
__device__ float g_coef [CB*CNC];
__device__ float g_sc   [(size_t)CB*CAH*CS*CS];
__device__ float g_slr  [MT*CD];
__device__ float g_gv   [MT*2*CD];
__device__ float g_cw1  [(size_t)8*128*(2*CD)];

// ---------------- bf16 split scratch (3x K) ----------------
__device__ __align__(16) __nv_bfloat16 g3_xn   [MT*3*CD];
__device__ __align__(16) __nv_bfloat16 g3_kv   [MT*3*CD];
__device__ __align__(16) __nv_bfloat16 g3_attn [MT*3*CD];
__device__ __align__(16) __nv_bfloat16 g3_fus  [MT*3*CD];
__device__ __align__(16) __nv_bfloat16 g3_h2   [(size_t)MT*3*CD];
__device__ __align__(16) __nv_bfloat16 g3_q    [MT*3*CD];
__device__ __align__(16) __nv_bfloat16 g3_k    [MT*3*CD];
__device__ __align__(16) __nv_bfloat16 g3_p    [(size_t)CB*CAH*CS*3*CS];
__device__ __align__(16) __nv_bfloat16 g3_vt   [(size_t)CB*CAH*CAHD*3*CS];
__device__ __align__(16) __nv_bfloat16 g3_wq   [(size_t)CD*3*CD];
__device__ __align__(16) __nv_bfloat16 g3_wk   [(size_t)CD*3*CD];
__device__ __align__(16) __nv_bfloat16 g3_wv   [(size_t)CD*3*CD];
__device__ __align__(16) __nv_bfloat16 g3_wo   [(size_t)CD*3*CD];
__device__ __align__(16) __nv_bfloat16 g3_wout [(size_t)CD*3*CD];
__device__ __align__(16) __nv_bfloat16 g3_wfgvb[(size_t)(2*CD)*3*CD];
__device__ __align__(16) __nv_bfloat16 g3_wt1  [(size_t)8*(2*CD)*768];
__device__ __align__(16) __nv_bfloat16 g3_cf   [(size_t)8*128*768];
__device__ __align__(16) __nv_bfloat16 g3_cw1t [(size_t)CB*(2*CD)*96];
__device__ __align__(16) __nv_bfloat16 g3_tsc  [(size_t)MT*96];

// ---------------- helpers ----------------
__device__ __forceinline__ uint32_t smem_u32(const void* p) {
    uint32_t a;
    asm("{ .reg .u64 t; cvta.to.shared.u64 t, %1; cvt.u32.u64 %0, t; }" : "=r"(a) : "l"(p));
    return a;
}
__device__ __forceinline__ void cp16(uint32_t dst, const void* src) {
    asm volatile("cp.async.cg.shared.global [%0], [%1], 16;" :: "r"(dst), "l"(src) : "memory");
}
__device__ __forceinline__ void cp_commit() { asm volatile("cp.async.commit_group;" ::: "memory"); }

__device__ __forceinline__ void ldm_x4(uint32_t addr, uint32_t& r0, uint32_t& r1,
                                       uint32_t& r2, uint32_t& r3) {
    asm volatile("ldmatrix.sync.aligned.m8n8.x4.shared.b16 {%0,%1,%2,%3}, [%4];"
                 : "=r"(r0), "=r"(r1), "=r"(r2), "=r"(r3) : "r"(addr));
}
__device__ __forceinline__ void mma16816(float* c, const uint32_t* a, const uint32_t* b) {
    asm volatile("mma.sync.aligned.m16n8k16.row.col.f32.bf16.bf16.f32 "
                 "{%0,%1,%2,%3}, {%4,%5,%6,%7}, {%8,%9}, {%0,%1,%2,%3};"
                 : "+f"(c[0]), "+f"(c[1]), "+f"(c[2]), "+f"(c[3])
                 : "r"(a[0]), "r"(a[1]), "r"(a[2]), "r"(a[3]), "r"(b[0]), "r"(b[1]));
}

__device__ __forceinline__ void split2(float a, __nv_bfloat16& hi, __nv_bfloat16& lo) {
    hi = __float2bfloat16(a);
    lo = __float2bfloat16(a - __bfloat162float(hi));
}

// ---------------- reductions (blockDim == 256) ----------------
__device__ __forceinline__ float warpSum(float v) {
    #pragma unroll
    for (int o = 16; o > 0; o >>= 1) v += __shfl_xor_sync(0xffffffffu, v, o);
    return v;
}
__device__ __forceinline__ float warpMax(float v) {
    #pragma unroll
    for (int o = 16; o > 0; o >>= 1) v = fmaxf(v, __shfl_xor_sync(0xffffffffu, v, o));
    return v;
}
__device__ __forceinline__ float blockSum(float v) {
    __shared__ float sh[8];
    v = warpSum(v);
    __syncthreads();
    if ((threadIdx.x & 31) == 0) sh[threadIdx.x >> 5] = v;
    __syncthreads();
    float r = sh[0];
    #pragma unroll
    for (int i = 1; i < 8; i++) r += sh[i];
    return r;
}
__device__ __forceinline__ float blockMax(float v) {
    __shared__ float shm[8];
    v = warpMax(v);
    __syncthreads();
    if ((threadIdx.x & 31) == 0) shm[threadIdx.x >> 5] = v;
    __syncthreads();
    float r = shm[0];
    #pragma unroll
    for (int i = 1; i < 8; i++) r = fmaxf(r, shm[i]);
    return r;
}

// =================== persistent HMMA bf16 GEMM (R6 mainloop, FROZEN) =======
#define ROWB 80
#define TILEB (128*ROWB)
#define STGB  (2*TILEB)
#define NSTG  4
#define MM_SMEM (NSTG*STGB)  // 81920

struct MMParams {
    const __nv_bfloat16* A;
    const __nv_bfloat16* B;
    float* C;
    const float* Add;
    __nv_bfloat16* S3;
    int lda, ldb, ldc, K3;
    float alpha;
    int bdiv;
    long long sAo, sAi, sBo, sBi, sCo, sCi;
    int tilesM, tilesN, total;
    int mode;        // 0 fp32 C(+Add); 1 q3 split; 2 k3 split; 3 attn3 split; 4 vt3 split
    int causal;
};

__global__ void __launch_bounds__(256, 2)
mm_bf16_kernel(MMParams p) {
    extern __shared__ __align__(128) char sm[];

    const int tid  = threadIdx.x, lane = tid & 31, wid = tid >> 5;
    const int wm   = wid >> 2, wn = wid & 3;
    const uint32_t sbase = smem_u32(sm);
    const int lrow = tid >> 1;
    const int lch  = (tid & 1) * 2;
    const uint32_t sAw = sbase + lrow * ROWB + lch * 16;
    const uint32_t sBw = sAw + TILEB;
    const int lr15 = lane & 15, lhi = lane >> 4;
    const uint32_t aoff = (uint32_t)((wm * 64 + lr15) * ROWB + lhi * 16);
    const uint32_t boff = (uint32_t)((wn * 32 + lr15) * ROWB + lhi * 16) + TILEB;
    const int tilesMN = p.tilesM * p.tilesN;
    const int NK = p.K3 / 32;

    for (int t = blockIdx.x; t < p.total; t += gridDim.x) {
        int z  = t / tilesMN;
        int r  = t - z * tilesMN;
        int ty = r / p.tilesN, tx = r - ty * p.tilesN;
        if (p.causal && tx > ty) continue;
        int zo = z / p.bdiv, zi = z - zo * p.bdiv;

        const __nv_bfloat16* Agb = p.A + zo * p.sAo + zi * p.sAi
                                   + (long long)(ty * 128 + lrow) * p.lda + lch * 8;
        const __nv_bfloat16* Bgb = p.B + zo * p.sBo + zi * p.sBi
                                   + (long long)(tx * 128 + lrow) * p.ldb + lch * 8;

        float acc[4][4][4];
        #pragma unroll
        for (int i = 0; i < 4; i++)
            #pragma unroll
            for (int j = 0; j < 4; j++)
                #pragma unroll
                for (int e = 0; e < 4; e++) acc[i][j][e] = 0.f;

        #pragma unroll
        for (int s = 0; s < 3; s++) {
            uint32_t o = (uint32_t)s * STGB;
            const __nv_bfloat16* Ag = Agb + s * 32;
            const __nv_bfloat16* Bg = Bgb + s * 32;
            cp16(sAw + o,      Ag);
            cp16(sAw + o + 16, Ag + 8);
            cp16(sBw + o,      Bg);
            cp16(sBw + o + 16, Bg + 8);
            cp_commit();
        }

        for (int kc = 0; kc < NK; kc++) {
            asm volatile("cp.async.wait_group 2;" ::: "memory");
            __syncthreads();
            if (kc + 3 < NK) {
                uint32_t o = (uint32_t)((kc + 3) & 3) * STGB;
                const __nv_bfloat16* Ag = Agb + (kc + 3) * 32;
                const __nv_bfloat16* Bg = Bgb + (kc + 3) * 32;
                cp16(sAw + o,      Ag);
                cp16(sAw + o + 16, Ag + 8);
                cp16(sBw + o,      Bg);
                cp16(sBw + o + 16, Bg + 8);
            }
            cp_commit();

            uint32_t sA = sbase + (uint32_t)(kc & 3) * STGB + aoff;
            uint32_t sB = sbase + (uint32_t)(kc & 3) * STGB + boff;
            #pragma unroll
            for (int ks = 0; ks < 2; ks++) {
                uint32_t a[4][4];
                #pragma unroll
                for (int mt = 0; mt < 4; mt++)
                    ldm_x4(sA + mt * (16 * ROWB) + ks * 32, a[mt][0], a[mt][1], a[mt][2], a[mt][3]);
                uint32_t b[4][2];
                #pragma unroll
                for (int bt = 0; bt < 2; bt++) {
                    uint32_t r0, r1, r2, r3;
                    ldm_x4(sB + bt * (16 * ROWB) + ks * 32, r0, r1, r2, r3);
                    b[bt * 2 + 0][0] = r0; b[bt * 2 + 0][1] = r2;
                    b[bt * 2 + 1][0] = r1; b[bt * 2 + 1][1] = r3;
                }
                #pragma unroll
                for (int mt = 0; mt < 4; mt++)
                    #pragma unroll
                    for (int nt = 0; nt < 4; nt++)
                        mma16816(acc[mt][nt], a[mt], b[nt]);
            }
        }
        __syncthreads();

        const int row0 = ty * 128, col0 = tx * 128;
        const int erow = wm * 64 + (lane >> 2);
        const int ecol = wn * 32 + (lane & 3) * 2;

        if (p.mode == 0) {
            long long coff = zo * p.sCo + zi * p.sCi;
            #pragma unroll
            for (int mt = 0; mt < 4; mt++)
                #pragma unroll
                for (int half = 0; half < 2; half++) {
                    int gr = row0 + erow + mt * 16 + half * 8;
                    long long rb = (long long)gr * p.ldc + col0 + ecol + coff;
                    #pragma unroll
                    for (int nt = 0; nt < 4; nt++) {
                        float2 v;
                        v.x = acc[mt][nt][half * 2 + 0] * p.alpha;
                        v.y = acc[mt][nt][half * 2 + 1] * p.alpha;
                        if (p.Add) {
                            float2 ad = *(const float2*)(p.Add + rb + nt * 8);
                            v.x += ad.x; v.y += ad.y;
                        }
                        *(float2*)(p.C + rb + nt * 8) = v;
                    }
                }
        } else if (p.mode == 3) {
            int b = z >> 4, h = z & 15;
            #pragma unroll
            for (int mt = 0; mt < 4; mt++)
                #pragma unroll
                for (int half = 0; half < 2; half++) {
                    int gr = row0 + erow + mt * 16 + half * 8;
                    long long base = ((long long)(b * CS + gr)) * (3LL * CD)
                                     + h * CAHD + col0 + ecol;
                    #pragma unroll
                    for (int nt = 0; nt < 4; nt++) {
                        float v0 = acc[mt][nt][half * 2 + 0];
                        float v1 = acc[mt][nt][half * 2 + 1];
                        __nv_bfloat16 h0, l0, h1, l1;
                        split2(v0, h0, l0); split2(v1, h1, l1);
                        __nv_bfloat162 hh = __nv_bfloat162(h0, h1);
                        __nv_bfloat162 ll = __nv_bfloat162(l0, l1);
                        __nv_bfloat16* d0 = (__nv_bfloat16*)(p.S3 + base + nt * 8);
                        *(__nv_bfloat162*)(d0)          = hh;
                        *(__nv_bfloat162*)(d0 + CD)     = hh;
                        *(__nv_bfloat162*)(d0 + 2 * CD) = ll;
                    }
                }
        } else if (p.mode == 4) {
            // V projection -> vt3: stage fp32 tile in smem, transposed split write
            float* st = (float*)sm;                 // [128][132]
            #pragma unroll
            for (int mt = 0; mt < 4; mt++)
                #pragma unroll
                for (int half = 0; half < 2; half++) {
                    int rr = erow + mt * 16 + half * 8;
                    #pragma unroll
                    for (int nt = 0; nt < 4; nt++) {
                        st[rr * 132 + ecol + nt * 8]     = acc[mt][nt][half * 2 + 0];
                        st[rr * 132 + ecol + nt * 8 + 1] = acc[mt][nt][half * 2 + 1];
                    }
                }
            __syncthreads();
            int b = row0 >> 9, seq0 = row0 & 511;   // 128-token tile within one batch
            int hh = col0 >> 7;                     // 128-col tile = one head
            long long bhbase = ((long long)(b * CAH + hh) * CAHD) * (3LL * CS);
            int sp  = tid & 63;                     // seq pair 0..63
            int n0t = tid >> 6;                     // 0..3
            #pragma unroll
            for (int it = 0; it < 32; it++) {
                int n = n0t + it * 4;
                float a0 = st[(2 * sp)     * 132 + n];
                float a1 = st[(2 * sp + 1) * 132 + n];
                __nv_bfloat16 h0, l0, h1, l1;
                split2(a0, h0, l0); split2(a1, h1, l1);
                __nv_bfloat162 hv(h0, h1), lv(l0, l1);
                long long base = bhbase + (long long)n * (3 * CS) + seq0 + 2 * sp;
                *(__nv_bfloat162*)(p.S3 + base)          = hv;
                *(__nv_bfloat162*)(p.S3 + base + CS)     = lv;
                *(__nv_bfloat162*)(p.S3 + base + 2 * CS) = hv;
            }
            __syncthreads();   // smem reused by next tile's prefetch
        } else {
            #pragma unroll
            for (int mt = 0; mt < 4; mt++)
                #pragma unroll
                for (int half = 0; half < 2; half++) {
                    int gr = row0 + erow + mt * 16 + half * 8;
                    long long rowb = (long long)gr * (3LL * CD);
                    #pragma unroll
                    for (int nt = 0; nt < 4; nt++) {
                        int n = col0 + ecol + nt * 8;
                        int hh_ = n >> 7, d = n & 127;
                        long long base = rowb + hh_ * 384 + d;
                        float v0 = acc[mt][nt][half * 2 + 0];
                        float v1 = acc[mt][nt][half * 2 + 1];
                        __nv_bfloat16 h0, l0, h1, l1;
                        split2(v0, h0, l0); split2(v1, h1, l1);
                        __nv_bfloat162 hv = __nv_bfloat162(h0, h1);
                        __nv_bfloat162 lv = __nv_bfloat162(l0, l1);
                        __nv_bfloat16* dp = p.S3 + base;
                        *(__nv_bfloat162*)(dp)       = hv;
                        *(__nv_bfloat162*)(dp + 128) = (p.mode == 1) ? hv : lv;
                        *(__nv_bfloat162*)(dp + 256) = (p.mode == 1) ? lv : hv;
                    }
                }
        }
    }
}

// =================== elementwise / prep kernels ===================

__global__ void rmsnorm_split_kernel(const float* __restrict__ in, const float* __restrict__ w,
                                     float* __restrict__ outf, __nv_bfloat16* __restrict__ out3,
                                     int Ktot, int colofs) {
    long long row = blockIdx.x;
    const float2* ip2 = (const float2*)(in + row * CD);
    const float2* w2  = (const float2*)w;
    float2 vals[4];
    float ss = 0.f;
    #pragma unroll
    for (int ii = 0; ii < 4; ii++) {
        int p = threadIdx.x + ii * 256;
        float2 u = ip2[p];
        vals[ii] = u;
        ss = fmaf(u.x, u.x, ss);
        ss = fmaf(u.y, u.y, ss);
    }
    ss = blockSum(ss);
    float rs = rsqrtf(ss * (1.f / CD) + 1e-6f);
    long long b3 = row * 3LL * Ktot + colofs;
    #pragma unroll
    for (int ii = 0; ii < 4; ii++) {
        int p = threadIdx.x + ii * 256;
        float2 wv = w2[p];
        float ux = vals[ii].x * rs * wv.x;
        float uy = vals[ii].y * rs * wv.y;
        if (outf) ((float2*)(outf + row * CD))[p] = make_float2(ux, uy);
        __nv_bfloat16 hx, lx, hy, ly;
        split2(ux, hx, lx); split2(uy, hy, ly);
        __nv_bfloat162 hv(hx, hy), lv(lx, ly);
        __nv_bfloat16* dp = out3 + b3 + 2 * p;
        *(__nv_bfloat162*)(dp)            = hv;
        *(__nv_bfloat162*)(dp + Ktot)     = hv;
        *(__nv_bfloat162*)(dp + 2 * Ktot) = lv;
    }
}

__global__ void colmean_kernel(const float* __restrict__ xn, float* __restrict__ xm) {
    int idx = blockIdx.x * blockDim.x + threadIdx.x;
    int b = idx / CD, d = idx % CD;
    float s = 0.f;
    for (int t = 0; t < CS; t++) s += xn[((long long)b * CS + t) * CD + d];
    xm[idx] = s * (1.f / CS);
}

__global__ void mlp2_kernel(const float* __restrict__ xm, const float* __restrict__ wc1,
                            const float* __restrict__ bc1, float* __restrict__ h) {
    int b = blockIdx.y, c = blockIdx.x * 256 + threadIdx.x;
    float s = 0.f;
    for (int k = 0; k < CD; k++) s = fmaf(xm[b * CD + k], wc1[(long long)k * CDQ + c], s);
    s += bc1[c];
    h[b * CDQ + c] = s / (1.f + expf(-s));
}

__global__ void coeff2_kernel(const float* __restrict__ h, const float* __restrict__ wc2,
                              const float* __restrict__ bc2, float* __restrict__ coef) {
    int b = blockIdx.y, c = blockIdx.x * 256 + threadIdx.x;
    float s = 0.f;
    for (int k = 0; k < CDQ; k++) s = fmaf(h[b * CDQ + k], wc2[(long long)k * CNC + c], s);
    s += bc2[c];
    int kdeg = (c / CHD) % CDEG;
    coef[(long long)b * CNC + c] = s * (0.1f / (float)(kdeg + 1));
}

__global__ void coeff3_kernel(const float* __restrict__ coef, const float* __restrict__ wnc,
                              __nv_bfloat16* __restrict__ cf3) {
    int h = blockIdx.x, r = blockIdx.y, i = threadIdx.x;
    float val = 0.f;
    if (r < 16) {
        int b = r >> 2, kd = r & 3;
        val = coef[(long long)b * CNC + (h * 4 + kd) * CHD + i] * wnc[h * CHD + i];
    }
    __nv_bfloat16 hi, lo; split2(val, hi, lo);
    long long base = ((long long)h * 128 + r) * 768;
    cf3[base + i] = hi;
    cf3[base + 256 + i] = hi;
    cf3[base + 512 + i] = lo;
}

__global__ void cheby3_kernel(const float* __restrict__ xn, const float* __restrict__ coef,
                              __nv_bfloat16* __restrict__ kv3, __nv_bfloat16* __restrict__ tsc3) {
    long long bs = blockIdx.x;
    int b = (int)(bs / CS);
    int w = threadIdx.x >> 5, lane = threadIdx.x & 31;
    const float2* u2 = (const float2*)(xn + bs * CD + w * CHD);
    float s = 0.f;
    #pragma unroll
    for (int pass = 0; pass < 4; pass++) {
        float2 u = u2[lane + pass * 32];
        s += u.x + u.y;
    }
    s = warpSum(s);
    float z = tanhf(s * (1.f / CHD));
    float T1 = z, T2 = 2.f * z * z - 1.f, T3 = 2.f * z * T2 - T1;
    const float2* cp2 = (const float2*)(coef + (((long long)b * CNH + w) * CDEG) * CHD);
    long long b3 = bs * (3LL * CD) + w * CHD;
    float ssloc = 0.f;
    #pragma unroll
    for (int pass = 0; pass < 4; pass++) {
        int p = lane + pass * 32;
        float2 c0 = cp2[p];
        float2 c1 = cp2[128 + p];
        float2 c2 = cp2[256 + p];
        float2 c3 = cp2[384 + p];
        float2 u  = u2[p];
        float ox = c0.x + T1 * c1.x + T2 * c2.x + T3 * c3.x;
        float oy = c0.y + T1 * c1.y + T2 * c2.y + T3 * c3.y;
        ssloc = fmaf(ox, ox, ssloc);
        ssloc = fmaf(oy, oy, ssloc);
        float vx = u.x + ox, vy = u.y + oy;
        __nv_bfloat16 hx, lx, hy, ly;
        split2(vx, hx, lx); split2(vy, hy, ly);
        __nv_bfloat162 hv(hx, hy), lv(lx, ly);
        __nv_bfloat16* dp = kv3 + b3 + 2 * p;
        *(__nv_bfloat162*)(dp)          = hv;
        *(__nv_bfloat162*)(dp + CD)     = hv;
        *(__nv_bfloat162*)(dp + 2 * CD) = lv;
    }
    float ss = blockSum(ssloc);
    float rs = rsqrtf(ss * (1.f / CD) + 1e-6f);
    if (lane < 4) {
        float tv = (lane == 0) ? 1.f : (lane == 1) ? T1 : (lane == 2) ? T2 : T3;
        tv *= rs;
        __nv_bfloat16 hi, lo; split2(tv, hi, lo);
        long long base = bs * 96 + w * 4 + lane;
        tsc3[base]      = hi;
        tsc3[base + 32] = hi;
        tsc3[base + 64] = lo;
    }
}

// batched 2048x2048 transpose + B-side split for 5 weights; 64(k)x32(n) tiles
struct T5Params {
    const float* W[5];
    __nv_bfloat16* Y[5];
};
__global__ void transpose_split5_kernel(T5Params p) {
    __shared__ float t[64][33];
    const float* W = p.W[blockIdx.z];
    __nv_bfloat16* Y = p.Y[blockIdx.z];
    int k0 = blockIdx.y * 64, n0 = blockIdx.x * 32;
    int tx = threadIdx.x, ty = threadIdx.y;
    #pragma unroll
    for (int i = 0; i < 8; i++) {
        int r = ty + i * 8;
        t[r][tx] = W[(long long)(k0 + r) * CD + n0 + tx];
    }
    __syncthreads();
    #pragma unroll
    for (int i = 0; i < 4; i++) {
        int c = ty + i * 8;
        int n = n0 + c;
        float a0 = t[2 * tx][c];
        float a1 = t[2 * tx + 1][c];
        __nv_bfloat16 h0, l0, h1, l1;
        split2(a0, h0, l0); split2(a1, h1, l1);
        __nv_bfloat162 hv(h0, h1), lv(l0, l1);
        long long base = (long long)n * 3 * CD + k0 + 2 * tx;
        *(__nv_bfloat162*)(Y + base)          = hv;
        *(__nv_bfloat162*)(Y + base + CD)     = lv;
        *(__nv_bfloat162*)(Y + base + 2 * CD) = hv;
    }
}

// general transpose + B-side split (fgv bottom): 64(k)x32(n) tiles
__global__ void transpose_split_kernel(const float* __restrict__ W, __nv_bfloat16* __restrict__ Y,
                                       int K, int N) {
    __shared__ float t[64][33];
    int k0 = blockIdx.y * 64, n0 = blockIdx.x * 32;
    int tx = threadIdx.x, ty = threadIdx.y;
    #pragma unroll
    for (int i = 0; i < 8; i++) {
        int r = ty + i * 8;
        t[r][tx] = W[(long long)(k0 + r) * N + n0 + tx];
    }
    __syncthreads();
    #pragma unroll
    for (int i = 0; i < 4; i++) {
        int c = ty + i * 8;
        int n = n0 + c;
        float a0 = t[2 * tx][c];
        float a1 = t[2 * tx + 1][c];
        __nv_bfloat16 h0, l0, h1, l1;
        split2(a0, h0, l0); split2(a1, h1, l1);
        __nv_bfloat162 hv(h0, h1), lv(l0, l1);
        long long base = (long long)n * 3 * K + k0 + 2 * tx;
        *(__nv_bfloat162*)(Y + base)         = hv;
        *(__nv_bfloat162*)(Y + base + K)     = lv;
        *(__nv_bfloat162*)(Y + base + 2 * K) = hv;
    }
}

// wfgv TOP half -> per-head transposed split; 64(k)x32(n) tiles
__global__ void wt1_split_kernel(const float* __restrict__ W, __nv_bfloat16* __restrict__ Y) {
    __shared__ float t[64][33];
    int k0 = blockIdx.y * 64, n0 = blockIdx.x * 32;
    int tx = threadIdx.x, ty = threadIdx.y;
    #pragma unroll
    for (int i = 0; i < 8; i++) {
        int r = ty + i * 8;
        t[r][tx] = W[(long long)(k0 + r) * (2 * CD) + n0 + tx];
    }
    __syncthreads();
    int h = k0 >> 8;
    int d0 = (k0 & 255) + 2 * tx;
    #pragma unroll
    for (int i = 0; i < 4; i++) {
        int c = ty + i * 8;
        int n = n0 + c;
        float a0 = t[2 * tx][c];
        float a1 = t[2 * tx + 1][c];
        __nv_bfloat16 h0, l0, h1, l1;
        split2(a0, h0, l0); split2(a1, h1, l1);
        __nv_bfloat162 hv(h0, h1), lv(l0, l1);
        long long base = ((long long)h * (2 * CD) + n) * 768 + d0;
        *(__nv_bfloat162*)(Y + base)       = hv;
        *(__nv_bfloat162*)(Y + base + 256) = lv;
        *(__nv_bfloat162*)(Y + base + 512) = hv;
    }
}

__global__ void cw1t_kernel(const float* __restrict__ CW1, __nv_bfloat16* __restrict__ Y) {
    int n = blockIdx.x * 256 + threadIdx.x;
    int b = blockIdx.y;
    long long obase = ((long long)b * (2 * CD) + n) * 96;
    #pragma unroll
    for (int j = 0; j < 32; j++) {
        int h = j >> 2, kd = j & 3;
        float v = CW1[(((long long)h * 128) + b * 4 + kd) * (2 * CD) + n];
        __nv_bfloat16 hi, lo; split2(v, hi, lo);
        Y[obase + j] = hi;
        Y[obase + 32 + j] = lo;
        Y[obase + 64 + j] = hi;
    }
}

__global__ void fuse_split_kernel(const float* __restrict__ gv, const float* __restrict__ wnp,
                                  __nv_bfloat16* __restrict__ out3) {
    long long row = blockIdx.x;
    const float2* gp2 = (const float2*)(gv + row * (2 * CD));
    const float2* w2  = (const float2*)wnp;
    float2 t[4];
    float ss = 0.f;
    #pragma unroll
    for (int ii = 0; ii < 4; ii++) {
        int p = threadIdx.x + ii * 256;
        float2 g = gp2[p];
        float2 v = gp2[CD / 2 + p];
        float ux = g.x / (1.f + expf(-g.x)) * v.x;
        float uy = g.y / (1.f + expf(-g.y)) * v.y;
        t[ii] = make_float2(ux, uy);
        ss = fmaf(ux, ux, ss);
        ss = fmaf(uy, uy, ss);
    }
    ss = blockSum(ss);
    float rs = rsqrtf(ss * (1.f / CD) + 1e-6f);
    long long b3 = row * (3LL * CD);
    #pragma unroll
    for (int ii = 0; ii < 4; ii++) {
        int p = threadIdx.x + ii * 256;
        float2 wv = w2[p];
        float ux = t[ii].x * rs * wv.x;
        float uy = t[ii].y * rs * wv.y;
        __nv_bfloat16 hx, lx, hy, ly;
        split2(ux, hx, lx); split2(uy, hy, ly);
        __nv_bfloat162 hv(hx, hy), lv(lx, ly);
        __nv_bfloat16* dp = out3 + b3 + 2 * p;
        *(__nv_bfloat162*)(dp)          = hv;
        *(__nv_bfloat162*)(dp + CD)     = hv;
        *(__nv_bfloat162*)(dp + 2 * CD) = lv;
    }
}

// causal softmax over 512-wide rows; vectorized pairs; split probs
__global__ void softmax_split_kernel(const float* __restrict__ sc, __nv_bfloat16* __restrict__ p3) {
    long long row = blockIdx.x;
    int i = (int)(row % CS);
    const float2* sp2 = (const float2*)(sc + row * CS);
    int j2 = threadIdx.x;
    int c0 = 2 * j2, c1 = 2 * j2 + 1;
    float2 sv = make_float2(0.f, 0.f);
    float m = -1e30f;
    if (c0 <= i) {
        sv = sp2[j2];
        m = fmaxf(m, sv.x);
        if (c1 <= i) m = fmaxf(m, sv.y);
    }
    m = blockMax(m);
    float ex = (c0 <= i) ? expf(sv.x - m) : 0.f;
    float ey = (c1 <= i) ? expf(sv.y - m) : 0.f;
    float s = blockSum(ex + ey);
    float inv = 1.f / s;
    float ux = ex * inv, uy = ey * inv;
    __nv_bfloat16 hx, lx, hy, ly;
    split2(ux, hx, lx); split2(uy, hy, ly);
    __nv_bfloat162 hv(hx, hy), lv(lx, ly);
    long long b3 = row * (3LL * CS);
    __nv_bfloat16* dp = p3 + b3 + c0;
    *(__nv_bfloat162*)(dp)          = hv;
    *(__nv_bfloat162*)(dp + CS)     = hv;
    *(__nv_bfloat162*)(dp + 2 * CS) = lv;
}

// ---------------- host ----------------
static int g_grid = 296;

static void mm(const __nv_bfloat16* A, const __nv_bfloat16* B, float* C, const float* Add,
               __nv_bfloat16* S3, int M, int N, int K3, int lda, int ldb, int ldc, float alpha,
               int bz, int bdiv, long long sAo, long long sAi, long long sBo, long long sBi,
               long long sCo, long long sCi, int mode, int causal) {
    MMParams p;
    p.A = A; p.B = B; p.C = C; p.Add = Add; p.S3 = S3;
    p.lda = lda; p.ldb = ldb; p.ldc = ldc; p.K3 = K3; p.alpha = alpha;
    p.bdiv = bdiv; p.sAo = sAo; p.sAi = sAi; p.sBo = sBo; p.sBi = sBi;
    p.sCo = sCo; p.sCi = sCi;
    p.tilesM = M / 128; p.tilesN = N / 128;
    p.total = bz * p.tilesM * p.tilesN;
    p.mode = mode; p.causal = causal;
    int grid = g_grid < p.total ? g_grid : p.total;
    mm_bf16_kernel<<<grid, 256, MM_SMEM>>>(p);
}

extern "C" void kernel_launch(void* const* d_in, const int* in_sizes, int n_in,
                              void* d_out, int out_size) {
    const float* x     = (const float*)d_in[0];
    const float* w_in  = (const float*)d_in[1];
    const float* wc1   = (const float*)d_in[6];
    const float* bc1   = (const float*)d_in[7];
    const float* wc2   = (const float*)d_in[8];
    const float* bc2   = (const float*)d_in[9];
    const float* wq    = (const float*)d_in[10];
    const float* wk    = (const float*)d_in[11];
    const float* wv    = (const float*)d_in[12];
    const float* wo    = (const float*)d_in[13];
    const float* w_nc  = (const float*)d_in[14];
    const float* w_ns  = (const float*)d_in[15];
    const float* w_fgv = (const float*)d_in[16];
    const float* w_np  = (const float*)d_in[17];
    const float* w_out = (const float*)d_in[18];
    float* out = (float*)d_out;

    int smc = 148;
    cudaDeviceGetAttribute(&smc, cudaDevAttrMultiProcessorCount, 0);
    g_grid = 2 * smc;

    cudaFuncSetAttribute(mm_bf16_kernel, cudaFuncAttributeMaxDynamicSharedMemorySize, MM_SMEM);

    float *xn, *xm, *hs, *coef, *sc, *slr, *gvb, *cw1;
    cudaGetSymbolAddress((void**)&xn,   g_xn);
    cudaGetSymbolAddress((void**)&xm,   g_xmean);
    cudaGetSymbolAddress((void**)&hs,   g_hs);
    cudaGetSymbolAddress((void**)&coef, g_coef);
    cudaGetSymbolAddress((void**)&sc,   g_sc);
    cudaGetSymbolAddress((void**)&slr,  g_slr);
    cudaGetSymbolAddress((void**)&gvb,  g_gv);
    cudaGetSymbolAddress((void**)&cw1,  g_cw1);

    __nv_bfloat16 *xn3, *kv3, *attn3, *fus3, *h23, *q3, *k3, *p3, *vt3;
    __nv_bfloat16 *wq3, *wk3, *wv3, *wo3, *wout3, *wfgvb3, *wt13, *cf3, *cw1t3, *tsc3;
    cudaGetSymbolAddress((void**)&xn3,    g3_xn);
    cudaGetSymbolAddress((void**)&kv3,    g3_kv);
    cudaGetSymbolAddress((void**)&attn3,  g3_attn);
    cudaGetSymbolAddress((void**)&fus3,   g3_fus);
    cudaGetSymbolAddress((void**)&h23,    g3_h2);
    cudaGetSymbolAddress((void**)&q3,     g3_q);
    cudaGetSymbolAddress((void**)&k3,     g3_k);
    cudaGetSymbolAddress((void**)&p3,     g3_p);
    cudaGetSymbolAddress((void**)&vt3,    g3_vt);
    cudaGetSymbolAddress((void**)&wq3,    g3_wq);
    cudaGetSymbolAddress((void**)&wk3,    g3_wk);
    cudaGetSymbolAddress((void**)&wv3,    g3_wv);
    cudaGetSymbolAddress((void**)&wo3,    g3_wo);
    cudaGetSymbolAddress((void**)&wout3,  g3_wout);
    cudaGetSymbolAddress((void**)&wfgvb3, g3_wfgvb);
    cudaGetSymbolAddress((void**)&wt13,   g3_wt1);
    cudaGetSymbolAddress((void**)&cf3,    g3_cf);
    cudaGetSymbolAddress((void**)&cw1t3,  g3_cw1t);
    cudaGetSymbolAddress((void**)&tsc3,   g3_tsc);

    dim3 tblk(32, 8);
    {
        T5Params tp;
        tp.W[0] = wq;    tp.Y[0] = wq3;
        tp.W[1] = wk;    tp.Y[1] = wk3;
        tp.W[2] = wv;    tp.Y[2] = wv3;
        tp.W[3] = wo;    tp.Y[3] = wo3;
        tp.W[4] = w_out; tp.Y[4] = wout3;
        transpose_split5_kernel<<<dim3(CD / 32, CD / 64, 5), tblk>>>(tp);
    }
    transpose_split_kernel<<<dim3((2 * CD) / 32, CD / 64), tblk>>>(
        w_fgv + (long long)CD * (2 * CD), wfgvb3, CD, 2 * CD);
    wt1_split_kernel<<<dim3((2 * CD) / 32, CD / 64), tblk>>>(w_fgv, wt13);

    rmsnorm_split_kernel<<<MT, 256>>>(x, w_in, xn, xn3, CD, 0);
    colmean_kernel<<<(CB * CD) / 256, 256>>>(xn, xm);
    mlp2_kernel<<<dim3(CDQ / 256, CB), 256>>>(xm, wc1, bc1, hs);
    coeff2_kernel<<<dim3(CNC / 256, CB), 256>>>(hs, wc2, bc2, coef);
    coeff3_kernel<<<dim3(8, 128), 256>>>(coef, w_nc, cf3);
    cheby3_kernel<<<MT, 256>>>(xn, coef, kv3, tsc3);

    // CW1 = coeff3 @ WT1 (batched over 8 heads)
    mm(cf3, wt13, cw1, 0, 0, 128, 2 * CD, 768, 768, 768, 2 * CD, 1.f,
       8, 1, (long long)128 * 768, 0, (long long)(2 * CD) * 768, 0,
       (long long)128 * (2 * CD), 0, 0, 0);
    cw1t_kernel<<<dim3((2 * CD) / 256, CB), 256>>>(cw1, cw1t3);

    // q/k projections -> head-split epilogues; v -> vt3 transposed split (mode 4)
    mm(xn3, wq3, 0, 0, q3, MT, CD, 3 * CD, 3 * CD, 3 * CD, CD, 1.f,
       1, 1, 0, 0, 0, 0, 0, 0, 1, 0);
    mm(kv3, wk3, 0, 0, k3, MT, CD, 3 * CD, 3 * CD, 3 * CD, CD, 1.f,
       1, 1, 0, 0, 0, 0, 0, 0, 2, 0);
    mm(kv3, wv3, 0, 0, vt3, MT, CD, 3 * CD, 3 * CD, 3 * CD, CD, 1.f,
       1, 1, 0, 0, 0, 0, 0, 0, 4, 0);

    // scores = q @ k^T / sqrt(hd) with causal tile skip
    mm(q3, k3, sc, 0, 0, CS, CS, 384, 3 * CD, 3 * CD, CS, 0.08838834764831845f,
       CB * CAH, CAH,
       (long long)CS * 3 * CD, 384,
       (long long)CS * 3 * CD, 384,
       (long long)CAH * CS * CS, (long long)CS * CS, 0, 1);

    softmax_split_kernel<<<CB * CAH * CS, 256>>>(sc, p3);

    // attn = P @ V -> attn3 split epilogue
    mm(p3, vt3, 0, 0, attn3, CS, CAHD, 3 * CS, 3 * CS, 3 * CS, CD, 1.f,
       CB * CAH, CAH,
       (long long)CAH * CS * 3 * CS, (long long)CS * 3 * CS,
       (long long)CAH * CAHD * 3 * CS, (long long)CAHD * 3 * CS,
       0, 0, 3, 0);

    // slr = attn @ wo
    mm(attn3, wo3, slr, 0, 0, MT, CD, 3 * CD, 3 * CD, 3 * CD, CD, 1.f,
       1, 1, 0, 0, 0, 0, 0, 0, 0, 0);

    // h2 = split(rmsnorm(slr, w_ns))
    rmsnorm_split_kernel<<<MT, 256>>>(slr, w_ns, 0, h23, CD, 0);

    // gv = (rs*T) @ CW1^T  (low-rank h1 path)
    mm(tsc3, cw1t3, gvb, 0, 0, CS, 2 * CD, 96, 96, 96, 2 * CD, 1.f,
       CB, 1, (long long)CS * 96, 0, (long long)(2 * CD) * 96, 0,
       (long long)CS * (2 * CD), 0, 0, 0);
    // gv += h2 @ wfgv_bottom
    mm(h23, wfgvb3, gvb, gvb, 0, MT, 2 * CD, 3 * CD, 3 * CD, 3 * CD, 2 * CD, 1.f,
       1, 1, 0, 0, 0, 0, 0, 0, 0, 0);

    fuse_split_kernel<<<MT, 256>>>(gvb, w_np, fus3);
    // out = x + fused @ w_out
    mm(fus3, wout3, out, x, 0, MT, CD, 3 * CD, 3 * CD, 3 * CD, CD, 1.f,
       1, 1, 0, 0, 0, 0, 0, 0, 0, 0);
}

// round 17
// speedup vs baseline: 1.0430x; 1.0336x over previous
#include <cuda_runtime.h>
#include <cuda_bf16.h>
#include <cstdint>
#include <math.h>

// ---------------- problem constants ----------------
#define CB   4
#define CS   512
#define CD   2048
#define CNH  8
#define CDEG 4
#define CHD  256
#define CAH  16
#define CAHD 128
#define CDQ  512
#define CNC  (CNH*CDEG*CHD)   // 8192
#define MT   (CB*CS)          // 2048 tokens

// ---------------- fp32 scratch ----------------
__device__ float g_xn   [MT*CD];
__device__ float g_xmean[CB*CD];
__device__ float g_hs   [CB*CDQ];
__device__ float g_coef [CB*CNC];
__device__ float g_sc   [(size_t)CB*CAH*CS*CS];
__device__ float g_slr  [MT*CD];
__device__ float g_gv   [MT*2*CD];
__device__ float g_cw1  [(size_t)8*128*(2*CD)];

// ---------------- bf16 split scratch (3x K) ----------------
__device__ __align__(16) __nv_bfloat16 g3_xn   [MT*3*CD];
__device__ __align__(16) __nv_bfloat16 g3_kv   [MT*3*CD];
__device__ __align__(16) __nv_bfloat16 g3_attn [MT*3*CD];
__device__ __align__(16) __nv_bfloat16 g3_fus  [MT*3*CD];
__device__ __align__(16) __nv_bfloat16 g3_h2   [(size_t)MT*3*CD];
__device__ __align__(16) __nv_bfloat16 g3_q    [MT*3*CD];
__device__ __align__(16) __nv_bfloat16 g3_k    [MT*3*CD];
__device__ __align__(16) __nv_bfloat16 g3_p    [(size_t)CB*CAH*CS*3*CS];
__device__ __align__(16) __nv_bfloat16 g3_vt   [(size_t)CB*CAH*CAHD*3*CS];
__device__ __align__(16) __nv_bfloat16 g3_wq   [(size_t)CD*3*CD];
__device__ __align__(16) __nv_bfloat16 g3_wk   [(size_t)CD*3*CD];
__device__ __align__(16) __nv_bfloat16 g3_wv   [(size_t)CD*3*CD];
__device__ __align__(16) __nv_bfloat16 g3_wo   [(size_t)CD*3*CD];
__device__ __align__(16) __nv_bfloat16 g3_wout [(size_t)CD*3*CD];
__device__ __align__(16) __nv_bfloat16 g3_wfgvb[(size_t)(2*CD)*3*CD];
__device__ __align__(16) __nv_bfloat16 g3_wt1  [(size_t)8*(2*CD)*768];
__device__ __align__(16) __nv_bfloat16 g3_cf   [(size_t)8*128*768];
__device__ __align__(16) __nv_bfloat16 g3_cw1t [(size_t)CB*(2*CD)*96];
__device__ __align__(16) __nv_bfloat16 g3_tsc  [(size_t)MT*96];

// ---------------- helpers ----------------
__device__ __forceinline__ uint32_t smem_u32(const void* p) {
    uint32_t a;
    asm("{ .reg .u64 t; cvta.to.shared.u64 t, %1; cvt.u32.u64 %0, t; }" : "=r"(a) : "l"(p));
    return a;
}
__device__ __forceinline__ void cp16(uint32_t dst, const void* src) {
    asm volatile("cp.async.cg.shared.global [%0], [%1], 16;" :: "r"(dst), "l"(src) : "memory");
}
__device__ __forceinline__ void cp_commit() { asm volatile("cp.async.commit_group;" ::: "memory"); }

__device__ __forceinline__ void ldm_x4(uint32_t addr, uint32_t& r0, uint32_t& r1,
                                       uint32_t& r2, uint32_t& r3) {
    asm volatile("ldmatrix.sync.aligned.m8n8.x4.shared.b16 {%0,%1,%2,%3}, [%4];"
                 : "=r"(r0), "=r"(r1), "=r"(r2), "=r"(r3) : "r"(addr));
}
__device__ __forceinline__ void mma16816(float* c, const uint32_t* a, const uint32_t* b) {
    asm volatile("mma.sync.aligned.m16n8k16.row.col.f32.bf16.bf16.f32 "
                 "{%0,%1,%2,%3}, {%4,%5,%6,%7}, {%8,%9}, {%0,%1,%2,%3};"
                 : "+f"(c[0]), "+f"(c[1]), "+f"(c[2]), "+f"(c[3])
                 : "r"(a[0]), "r"(a[1]), "r"(a[2]), "r"(a[3]), "r"(b[0]), "r"(b[1]));
}

__device__ __forceinline__ void split2(float a, __nv_bfloat16& hi, __nv_bfloat16& lo) {
    hi = __float2bfloat16(a);
    lo = __float2bfloat16(a - __bfloat162float(hi));
}

// ---------------- reductions (blockDim == 256) ----------------
__device__ __forceinline__ float warpSum(float v) {
    #pragma unroll
    for (int o = 16; o > 0; o >>= 1) v += __shfl_xor_sync(0xffffffffu, v, o);
    return v;
}
__device__ __forceinline__ float warpMax(float v) {
    #pragma unroll
    for (int o = 16; o > 0; o >>= 1) v = fmaxf(v, __shfl_xor_sync(0xffffffffu, v, o));
    return v;
}
__device__ __forceinline__ float blockSum(float v) {
    __shared__ float sh[8];
    v = warpSum(v);
    __syncthreads();
    if ((threadIdx.x & 31) == 0) sh[threadIdx.x >> 5] = v;
    __syncthreads();
    float r = sh[0];
    #pragma unroll
    for (int i = 1; i < 8; i++) r += sh[i];
    return r;
}
__device__ __forceinline__ float blockMax(float v) {
    __shared__ float shm[8];
    v = warpMax(v);
    __syncthreads();
    if ((threadIdx.x & 31) == 0) shm[threadIdx.x >> 5] = v;
    __syncthreads();
    float r = shm[0];
    #pragma unroll
    for (int i = 1; i < 8; i++) r = fmaxf(r, shm[i]);
    return r;
}

// =================== persistent HMMA bf16 GEMM (R6 mainloop, FROZEN) =======
#define ROWB 80
#define TILEB (128*ROWB)
#define STGB  (2*TILEB)
#define NSTG  4
#define MM_SMEM (NSTG*STGB)  // 81920

struct MMParams {
    const __nv_bfloat16* A;
    const __nv_bfloat16* B;
    float* C;
    const float* Add;
    __nv_bfloat16* S3;
    int lda, ldb, ldc, K3;
    float alpha;
    int bdiv;
    long long sAo, sAi, sBo, sBi, sCo, sCi;
    int tilesM, tilesN, total;
    int mode;        // 0 fp32 C(+Add); 1 q3; 2 k3; 3 attn3; 4 vt3
    int causal;
    int fused;       // qkv fused launch: per-z tables below
    const __nv_bfloat16* Az[3];
    const __nv_bfloat16* Bz[3];
    __nv_bfloat16* S3z[3];
    int modez[3];
};

__global__ void __launch_bounds__(256, 2)
mm_bf16_kernel(MMParams p) {
    extern __shared__ __align__(128) char sm[];

    const int tid  = threadIdx.x, lane = tid & 31, wid = tid >> 5;
    const int wm   = wid >> 2, wn = wid & 3;
    const uint32_t sbase = smem_u32(sm);
    const int lrow = tid >> 1;
    const int lch  = (tid & 1) * 2;
    const uint32_t sAw = sbase + lrow * ROWB + lch * 16;
    const uint32_t sBw = sAw + TILEB;
    const int lr15 = lane & 15, lhi = lane >> 4;
    const uint32_t aoff = (uint32_t)((wm * 64 + lr15) * ROWB + lhi * 16);
    const uint32_t boff = (uint32_t)((wn * 32 + lr15) * ROWB + lhi * 16) + TILEB;
    const int tilesMN = p.tilesM * p.tilesN;
    const int NK = p.K3 / 32;

    for (int t = blockIdx.x; t < p.total; t += gridDim.x) {
        int z  = t / tilesMN;
        int r  = t - z * tilesMN;
        int ty = r / p.tilesN, tx = r - ty * p.tilesN;
        if (p.causal && tx > ty) continue;
        int zo = z / p.bdiv, zi = z - zo * p.bdiv;

        const __nv_bfloat16* Abase;
        const __nv_bfloat16* Bbase;
        __nv_bfloat16* S3o;
        int mode;
        if (p.fused) {
            Abase = p.Az[z];
            Bbase = p.Bz[z];
            S3o   = p.S3z[z];
            mode  = p.modez[z];
        } else {
            Abase = p.A + zo * p.sAo + zi * p.sAi;
            Bbase = p.B + zo * p.sBo + zi * p.sBi;
            S3o   = p.S3;
            mode  = p.mode;
        }

        const __nv_bfloat16* Agb = Abase + (long long)(ty * 128 + lrow) * p.lda + lch * 8;
        const __nv_bfloat16* Bgb = Bbase + (long long)(tx * 128 + lrow) * p.ldb + lch * 8;

        float acc[4][4][4];
        #pragma unroll
        for (int i = 0; i < 4; i++)
            #pragma unroll
            for (int j = 0; j < 4; j++)
                #pragma unroll
                for (int e = 0; e < 4; e++) acc[i][j][e] = 0.f;

        #pragma unroll
        for (int s = 0; s < 3; s++) {
            uint32_t o = (uint32_t)s * STGB;
            const __nv_bfloat16* Ag = Agb + s * 32;
            const __nv_bfloat16* Bg = Bgb + s * 32;
            cp16(sAw + o,      Ag);
            cp16(sAw + o + 16, Ag + 8);
            cp16(sBw + o,      Bg);
            cp16(sBw + o + 16, Bg + 8);
            cp_commit();
        }

        for (int kc = 0; kc < NK; kc++) {
            asm volatile("cp.async.wait_group 2;" ::: "memory");
            __syncthreads();
            if (kc + 3 < NK) {
                uint32_t o = (uint32_t)((kc + 3) & 3) * STGB;
                const __nv_bfloat16* Ag = Agb + (kc + 3) * 32;
                const __nv_bfloat16* Bg = Bgb + (kc + 3) * 32;
                cp16(sAw + o,      Ag);
                cp16(sAw + o + 16, Ag + 8);
                cp16(sBw + o,      Bg);
                cp16(sBw + o + 16, Bg + 8);
            }
            cp_commit();

            uint32_t sA = sbase + (uint32_t)(kc & 3) * STGB + aoff;
            uint32_t sB = sbase + (uint32_t)(kc & 3) * STGB + boff;
            #pragma unroll
            for (int ks = 0; ks < 2; ks++) {
                uint32_t a[4][4];
                #pragma unroll
                for (int mt = 0; mt < 4; mt++)
                    ldm_x4(sA + mt * (16 * ROWB) + ks * 32, a[mt][0], a[mt][1], a[mt][2], a[mt][3]);
                uint32_t b[4][2];
                #pragma unroll
                for (int bt = 0; bt < 2; bt++) {
                    uint32_t r0, r1, r2, r3;
                    ldm_x4(sB + bt * (16 * ROWB) + ks * 32, r0, r1, r2, r3);
                    b[bt * 2 + 0][0] = r0; b[bt * 2 + 0][1] = r2;
                    b[bt * 2 + 1][0] = r1; b[bt * 2 + 1][1] = r3;
                }
                #pragma unroll
                for (int mt = 0; mt < 4; mt++)
                    #pragma unroll
                    for (int nt = 0; nt < 4; nt++)
                        mma16816(acc[mt][nt], a[mt], b[nt]);
            }
        }
        __syncthreads();

        const int row0 = ty * 128, col0 = tx * 128;
        const int erow = wm * 64 + (lane >> 2);
        const int ecol = wn * 32 + (lane & 3) * 2;

        if (mode == 0) {
            long long coff = zo * p.sCo + zi * p.sCi;
            #pragma unroll
            for (int mt = 0; mt < 4; mt++)
                #pragma unroll
                for (int half = 0; half < 2; half++) {
                    int gr = row0 + erow + mt * 16 + half * 8;
                    long long rb = (long long)gr * p.ldc + col0 + ecol + coff;
                    #pragma unroll
                    for (int nt = 0; nt < 4; nt++) {
                        float2 v;
                        v.x = acc[mt][nt][half * 2 + 0] * p.alpha;
                        v.y = acc[mt][nt][half * 2 + 1] * p.alpha;
                        if (p.Add) {
                            float2 ad = *(const float2*)(p.Add + rb + nt * 8);
                            v.x += ad.x; v.y += ad.y;
                        }
                        *(float2*)(p.C + rb + nt * 8) = v;
                    }
                }
        } else if (mode == 3) {
            int b = z >> 4, h = z & 15;
            #pragma unroll
            for (int mt = 0; mt < 4; mt++)
                #pragma unroll
                for (int half = 0; half < 2; half++) {
                    int gr = row0 + erow + mt * 16 + half * 8;
                    long long base = ((long long)(b * CS + gr)) * (3LL * CD)
                                     + h * CAHD + col0 + ecol;
                    #pragma unroll
                    for (int nt = 0; nt < 4; nt++) {
                        float v0 = acc[mt][nt][half * 2 + 0];
                        float v1 = acc[mt][nt][half * 2 + 1];
                        __nv_bfloat16 h0, l0, h1, l1;
                        split2(v0, h0, l0); split2(v1, h1, l1);
                        __nv_bfloat162 hh = __nv_bfloat162(h0, h1);
                        __nv_bfloat162 ll = __nv_bfloat162(l0, l1);
                        __nv_bfloat16* d0 = (__nv_bfloat16*)(S3o + base + nt * 8);
                        *(__nv_bfloat162*)(d0)          = hh;
                        *(__nv_bfloat162*)(d0 + CD)     = hh;
                        *(__nv_bfloat162*)(d0 + 2 * CD) = ll;
                    }
                }
        } else if (mode == 4) {
            // V projection -> vt3: stage fp32 tile in smem, transposed split write
            float* st = (float*)sm;                 // [128][132]
            #pragma unroll
            for (int mt = 0; mt < 4; mt++)
                #pragma unroll
                for (int half = 0; half < 2; half++) {
                    int rr = erow + mt * 16 + half * 8;
                    #pragma unroll
                    for (int nt = 0; nt < 4; nt++) {
                        st[rr * 132 + ecol + nt * 8]     = acc[mt][nt][half * 2 + 0];
                        st[rr * 132 + ecol + nt * 8 + 1] = acc[mt][nt][half * 2 + 1];
                    }
                }
            __syncthreads();
            int b = row0 >> 9, seq0 = row0 & 511;
            int hh = col0 >> 7;
            long long bhbase = ((long long)(b * CAH + hh) * CAHD) * (3LL * CS);
            int sp  = tid & 63;
            int n0t = tid >> 6;
            #pragma unroll
            for (int it = 0; it < 32; it++) {
                int n = n0t + it * 4;
                float a0 = st[(2 * sp)     * 132 + n];
                float a1 = st[(2 * sp + 1) * 132 + n];
                __nv_bfloat16 h0, l0, h1, l1;
                split2(a0, h0, l0); split2(a1, h1, l1);
                __nv_bfloat162 hv(h0, h1), lv(l0, l1);
                long long base = bhbase + (long long)n * (3 * CS) + seq0 + 2 * sp;
                *(__nv_bfloat162*)(S3o + base)          = hv;
                *(__nv_bfloat162*)(S3o + base + CS)     = lv;
                *(__nv_bfloat162*)(S3o + base + 2 * CS) = hv;
            }
            __syncthreads();
        } else {
            #pragma unroll
            for (int mt = 0; mt < 4; mt++)
                #pragma unroll
                for (int half = 0; half < 2; half++) {
                    int gr = row0 + erow + mt * 16 + half * 8;
                    long long rowb = (long long)gr * (3LL * CD);
                    #pragma unroll
                    for (int nt = 0; nt < 4; nt++) {
                        int n = col0 + ecol + nt * 8;
                        int hh_ = n >> 7, d = n & 127;
                        long long base = rowb + hh_ * 384 + d;
                        float v0 = acc[mt][nt][half * 2 + 0];
                        float v1 = acc[mt][nt][half * 2 + 1];
                        __nv_bfloat16 h0, l0, h1, l1;
                        split2(v0, h0, l0); split2(v1, h1, l1);
                        __nv_bfloat162 hv = __nv_bfloat162(h0, h1);
                        __nv_bfloat162 lv = __nv_bfloat162(l0, l1);
                        __nv_bfloat16* dp = S3o + base;
                        *(__nv_bfloat162*)(dp)       = hv;
                        *(__nv_bfloat162*)(dp + 128) = (mode == 1) ? hv : lv;
                        *(__nv_bfloat162*)(dp + 256) = (mode == 1) ? lv : hv;
                    }
                }
        }
    }
}

// =================== elementwise / prep kernels ===================

__global__ void rmsnorm_split_kernel(const float* __restrict__ in, const float* __restrict__ w,
                                     float* __restrict__ outf, __nv_bfloat16* __restrict__ out3,
                                     int Ktot, int colofs) {
    long long row = blockIdx.x;
    const float2* ip2 = (const float2*)(in + row * CD);
    const float2* w2  = (const float2*)w;
    float2 vals[4];
    float ss = 0.f;
    #pragma unroll
    for (int ii = 0; ii < 4; ii++) {
        int p = threadIdx.x + ii * 256;
        float2 u = ip2[p];
        vals[ii] = u;
        ss = fmaf(u.x, u.x, ss);
        ss = fmaf(u.y, u.y, ss);
    }
    ss = blockSum(ss);
    float rs = rsqrtf(ss * (1.f / CD) + 1e-6f);
    long long b3 = row * 3LL * Ktot + colofs;
    #pragma unroll
    for (int ii = 0; ii < 4; ii++) {
        int p = threadIdx.x + ii * 256;
        float2 wv = w2[p];
        float ux = vals[ii].x * rs * wv.x;
        float uy = vals[ii].y * rs * wv.y;
        if (outf) ((float2*)(outf + row * CD))[p] = make_float2(ux, uy);
        __nv_bfloat16 hx, lx, hy, ly;
        split2(ux, hx, lx); split2(uy, hy, ly);
        __nv_bfloat162 hv(hx, hy), lv(lx, ly);
        __nv_bfloat16* dp = out3 + b3 + 2 * p;
        *(__nv_bfloat162*)(dp)            = hv;
        *(__nv_bfloat162*)(dp + Ktot)     = hv;
        *(__nv_bfloat162*)(dp + 2 * Ktot) = lv;
    }
}

__global__ void colmean_kernel(const float* __restrict__ xn, float* __restrict__ xm) {
    int idx = blockIdx.x * blockDim.x + threadIdx.x;
    int b = idx / CD, d = idx % CD;
    const float* base = xn + (long long)b * CS * CD + d;
    float s0 = 0.f, s1 = 0.f, s2 = 0.f, s3 = 0.f;
    for (int t = 0; t < CS; t += 4) {
        s0 += base[(long long)t * CD];
        s1 += base[(long long)(t + 1) * CD];
        s2 += base[(long long)(t + 2) * CD];
        s3 += base[(long long)(t + 3) * CD];
    }
    xm[idx] = (s0 + s1 + s2 + s3) * (1.f / CS);
}

__global__ void mlp2_kernel(const float* __restrict__ xm, const float* __restrict__ wc1,
                            const float* __restrict__ bc1, float* __restrict__ h) {
    int b = blockIdx.y, c = blockIdx.x * 256 + threadIdx.x;
    float s0 = 0.f, s1 = 0.f, s2 = 0.f, s3 = 0.f;
    const float* xb = xm + b * CD;
    for (int k = 0; k < CD; k += 4) {
        s0 = fmaf(xb[k],     wc1[(long long)k * CDQ + c],       s0);
        s1 = fmaf(xb[k + 1], wc1[(long long)(k + 1) * CDQ + c], s1);
        s2 = fmaf(xb[k + 2], wc1[(long long)(k + 2) * CDQ + c], s2);
        s3 = fmaf(xb[k + 3], wc1[(long long)(k + 3) * CDQ + c], s3);
    }
    float s = (s0 + s1) + (s2 + s3) + bc1[c];
    h[b * CDQ + c] = s / (1.f + expf(-s));
}

__global__ void coeff2_kernel(const float* __restrict__ h, const float* __restrict__ wc2,
                              const float* __restrict__ bc2, float* __restrict__ coef) {
    int b = blockIdx.y, c = blockIdx.x * 256 + threadIdx.x;
    float s0 = 0.f, s1 = 0.f, s2 = 0.f, s3 = 0.f;
    const float* hb = h + b * CDQ;
    for (int k = 0; k < CDQ; k += 4) {
        s0 = fmaf(hb[k],     wc2[(long long)k * CNC + c],       s0);
        s1 = fmaf(hb[k + 1], wc2[(long long)(k + 1) * CNC + c], s1);
        s2 = fmaf(hb[k + 2], wc2[(long long)(k + 2) * CNC + c], s2);
        s3 = fmaf(hb[k + 3], wc2[(long long)(k + 3) * CNC + c], s3);
    }
    float s = (s0 + s1) + (s2 + s3) + bc2[c];
    int kdeg = (c / CHD) % CDEG;
    coef[(long long)b * CNC + c] = s * (0.1f / (float)(kdeg + 1));
}

__global__ void coeff3_kernel(const float* __restrict__ coef, const float* __restrict__ wnc,
                              __nv_bfloat16* __restrict__ cf3) {
    int h = blockIdx.x, r = blockIdx.y, i = threadIdx.x;
    float val = 0.f;
    if (r < 16) {
        int b = r >> 2, kd = r & 3;
        val = coef[(long long)b * CNC + (h * 4 + kd) * CHD + i] * wnc[h * CHD + i];
    }
    __nv_bfloat16 hi, lo; split2(val, hi, lo);
    long long base = ((long long)h * 128 + r) * 768;
    cf3[base + i] = hi;
    cf3[base + 256 + i] = hi;
    cf3[base + 512 + i] = lo;
}

__global__ void cheby3_kernel(const float* __restrict__ xn, const float* __restrict__ coef,
                              __nv_bfloat16* __restrict__ kv3, __nv_bfloat16* __restrict__ tsc3) {
    long long bs = blockIdx.x;
    int b = (int)(bs / CS);
    int w = threadIdx.x >> 5, lane = threadIdx.x & 31;
    const float2* u2 = (const float2*)(xn + bs * CD + w * CHD);
    float s = 0.f;
    #pragma unroll
    for (int pass = 0; pass < 4; pass++) {
        float2 u = u2[lane + pass * 32];
        s += u.x + u.y;
    }
    s = warpSum(s);
    float z = tanhf(s * (1.f / CHD));
    float T1 = z, T2 = 2.f * z * z - 1.f, T3 = 2.f * z * T2 - T1;
    const float2* cp2 = (const float2*)(coef + (((long long)b * CNH + w) * CDEG) * CHD);
    long long b3 = bs * (3LL * CD) + w * CHD;
    float ssloc = 0.f;
    #pragma unroll
    for (int pass = 0; pass < 4; pass++) {
        int p = lane + pass * 32;
        float2 c0 = cp2[p];
        float2 c1 = cp2[128 + p];
        float2 c2 = cp2[256 + p];
        float2 c3 = cp2[384 + p];
        float2 u  = u2[p];
        float ox = c0.x + T1 * c1.x + T2 * c2.x + T3 * c3.x;
        float oy = c0.y + T1 * c1.y + T2 * c2.y + T3 * c3.y;
        ssloc = fmaf(ox, ox, ssloc);
        ssloc = fmaf(oy, oy, ssloc);
        float vx = u.x + ox, vy = u.y + oy;
        __nv_bfloat16 hx, lx, hy, ly;
        split2(vx, hx, lx); split2(vy, hy, ly);
        __nv_bfloat162 hv(hx, hy), lv(lx, ly);
        __nv_bfloat16* dp = kv3 + b3 + 2 * p;
        *(__nv_bfloat162*)(dp)          = hv;
        *(__nv_bfloat162*)(dp + CD)     = hv;
        *(__nv_bfloat162*)(dp + 2 * CD) = lv;
    }
    float ss = blockSum(ssloc);
    float rs = rsqrtf(ss * (1.f / CD) + 1e-6f);
    if (lane < 4) {
        float tv = (lane == 0) ? 1.f : (lane == 1) ? T1 : (lane == 2) ? T2 : T3;
        tv *= rs;
        __nv_bfloat16 hi, lo; split2(tv, hi, lo);
        long long base = bs * 96 + w * 4 + lane;
        tsc3[base]      = hi;
        tsc3[base + 32] = hi;
        tsc3[base + 64] = lo;
    }
}

// batched 2048x2048 transpose + B-side split for 5 weights; 64(k)x32(n) tiles
struct T5Params {
    const float* W[5];
    __nv_bfloat16* Y[5];
};
__global__ void transpose_split5_kernel(T5Params p) {
    __shared__ float t[64][33];
    const float* W = p.W[blockIdx.z];
    __nv_bfloat16* Y = p.Y[blockIdx.z];
    int k0 = blockIdx.y * 64, n0 = blockIdx.x * 32;
    int tx = threadIdx.x, ty = threadIdx.y;
    #pragma unroll
    for (int i = 0; i < 8; i++) {
        int r = ty + i * 8;
        t[r][tx] = W[(long long)(k0 + r) * CD + n0 + tx];
    }
    __syncthreads();
    #pragma unroll
    for (int i = 0; i < 4; i++) {
        int c = ty + i * 8;
        int n = n0 + c;
        float a0 = t[2 * tx][c];
        float a1 = t[2 * tx + 1][c];
        __nv_bfloat16 h0, l0, h1, l1;
        split2(a0, h0, l0); split2(a1, h1, l1);
        __nv_bfloat162 hv(h0, h1), lv(l0, l1);
        long long base = (long long)n * 3 * CD + k0 + 2 * tx;
        *(__nv_bfloat162*)(Y + base)          = hv;
        *(__nv_bfloat162*)(Y + base + CD)     = lv;
        *(__nv_bfloat162*)(Y + base + 2 * CD) = hv;
    }
}

// general transpose + B-side split (fgv bottom): 64(k)x32(n) tiles
__global__ void transpose_split_kernel(const float* __restrict__ W, __nv_bfloat16* __restrict__ Y,
                                       int K, int N) {
    __shared__ float t[64][33];
    int k0 = blockIdx.y * 64, n0 = blockIdx.x * 32;
    int tx = threadIdx.x, ty = threadIdx.y;
    #pragma unroll
    for (int i = 0; i < 8; i++) {
        int r = ty + i * 8;
        t[r][tx] = W[(long long)(k0 + r) * N + n0 + tx];
    }
    __syncthreads();
    #pragma unroll
    for (int i = 0; i < 4; i++) {
        int c = ty + i * 8;
        int n = n0 + c;
        float a0 = t[2 * tx][c];
        float a1 = t[2 * tx + 1][c];
        __nv_bfloat16 h0, l0, h1, l1;
        split2(a0, h0, l0); split2(a1, h1, l1);
        __nv_bfloat162 hv(h0, h1), lv(l0, l1);
        long long base = (long long)n * 3 * K + k0 + 2 * tx;
        *(__nv_bfloat162*)(Y + base)         = hv;
        *(__nv_bfloat162*)(Y + base + K)     = lv;
        *(__nv_bfloat162*)(Y + base + 2 * K) = hv;
    }
}

// wfgv TOP half -> per-head transposed split; 64(k)x32(n) tiles
__global__ void wt1_split_kernel(const float* __restrict__ W, __nv_bfloat16* __restrict__ Y) {
    __shared__ float t[64][33];
    int k0 = blockIdx.y * 64, n0 = blockIdx.x * 32;
    int tx = threadIdx.x, ty = threadIdx.y;
    #pragma unroll
    for (int i = 0; i < 8; i++) {
        int r = ty + i * 8;
        t[r][tx] = W[(long long)(k0 + r) * (2 * CD) + n0 + tx];
    }
    __syncthreads();
    int h = k0 >> 8;
    int d0 = (k0 & 255) + 2 * tx;
    #pragma unroll
    for (int i = 0; i < 4; i++) {
        int c = ty + i * 8;
        int n = n0 + c;
        float a0 = t[2 * tx][c];
        float a1 = t[2 * tx + 1][c];
        __nv_bfloat16 h0, l0, h1, l1;
        split2(a0, h0, l0); split2(a1, h1, l1);
        __nv_bfloat162 hv(h0, h1), lv(l0, l1);
        long long base = ((long long)h * (2 * CD) + n) * 768 + d0;
        *(__nv_bfloat162*)(Y + base)       = hv;
        *(__nv_bfloat162*)(Y + base + 256) = lv;
        *(__nv_bfloat162*)(Y + base + 512) = hv;
    }
}

__global__ void cw1t_kernel(const float* __restrict__ CW1, __nv_bfloat16* __restrict__ Y) {
    int n = blockIdx.x * 256 + threadIdx.x;
    int b = blockIdx.y;
    long long obase = ((long long)b * (2 * CD) + n) * 96;
    #pragma unroll
    for (int j = 0; j < 32; j++) {
        int h = j >> 2, kd = j & 3;
        float v = CW1[(((long long)h * 128) + b * 4 + kd) * (2 * CD) + n];
        __nv_bfloat16 hi, lo; split2(v, hi, lo);
        Y[obase + j] = hi;
        Y[obase + 32 + j] = lo;
        Y[obase + 64 + j] = hi;
    }
}

__global__ void fuse_split_kernel(const float* __restrict__ gv, const float* __restrict__ wnp,
                                  __nv_bfloat16* __restrict__ out3) {
    long long row = blockIdx.x;
    const float2* gp2 = (const float2*)(gv + row * (2 * CD));
    const float2* w2  = (const float2*)wnp;
    float2 t[4];
    float ss = 0.f;
    #pragma unroll
    for (int ii = 0; ii < 4; ii++) {
        int p = threadIdx.x + ii * 256;
        float2 g = gp2[p];
        float2 v = gp2[CD / 2 + p];
        float ux = g.x / (1.f + expf(-g.x)) * v.x;
        float uy = g.y / (1.f + expf(-g.y)) * v.y;
        t[ii] = make_float2(ux, uy);
        ss = fmaf(ux, ux, ss);
        ss = fmaf(uy, uy, ss);
    }
    ss = blockSum(ss);
    float rs = rsqrtf(ss * (1.f / CD) + 1e-6f);
    long long b3 = row * (3LL * CD);
    #pragma unroll
    for (int ii = 0; ii < 4; ii++) {
        int p = threadIdx.x + ii * 256;
        float2 wv = w2[p];
        float ux = t[ii].x * rs * wv.x;
        float uy = t[ii].y * rs * wv.y;
        __nv_bfloat16 hx, lx, hy, ly;
        split2(ux, hx, lx); split2(uy, hy, ly);
        __nv_bfloat162 hv(hx, hy), lv(lx, ly);
        __nv_bfloat16* dp = out3 + b3 + 2 * p;
        *(__nv_bfloat162*)(dp)          = hv;
        *(__nv_bfloat162*)(dp + CD)     = hv;
        *(__nv_bfloat162*)(dp + 2 * CD) = lv;
    }
}

// causal softmax over 512-wide rows; vectorized pairs; split probs
__global__ void softmax_split_kernel(const float* __restrict__ sc, __nv_bfloat16* __restrict__ p3) {
    long long row = blockIdx.x;
    int i = (int)(row % CS);
    const float2* sp2 = (const float2*)(sc + row * CS);
    int j2 = threadIdx.x;
    int c0 = 2 * j2, c1 = 2 * j2 + 1;
    float2 sv = make_float2(0.f, 0.f);
    float m = -1e30f;
    if (c0 <= i) {
        sv = sp2[j2];
        m = fmaxf(m, sv.x);
        if (c1 <= i) m = fmaxf(m, sv.y);
    }
    m = blockMax(m);
    float ex = (c0 <= i) ? expf(sv.x - m) : 0.f;
    float ey = (c1 <= i) ? expf(sv.y - m) : 0.f;
    float s = blockSum(ex + ey);
    float inv = 1.f / s;
    float ux = ex * inv, uy = ey * inv;
    __nv_bfloat16 hx, lx, hy, ly;
    split2(ux, hx, lx); split2(uy, hy, ly);
    __nv_bfloat162 hv(hx, hy), lv(lx, ly);
    long long b3 = row * (3LL * CS);
    __nv_bfloat16* dp = p3 + b3 + c0;
    *(__nv_bfloat162*)(dp)          = hv;
    *(__nv_bfloat162*)(dp + CS)     = hv;
    *(__nv_bfloat162*)(dp + 2 * CS) = lv;
}

// ---------------- host ----------------
static int g_grid = 296;

static void mm(const __nv_bfloat16* A, const __nv_bfloat16* B, float* C, const float* Add,
               __nv_bfloat16* S3, int M, int N, int K3, int lda, int ldb, int ldc, float alpha,
               int bz, int bdiv, long long sAo, long long sAi, long long sBo, long long sBi,
               long long sCo, long long sCi, int mode, int causal) {
    MMParams p;
    p.A = A; p.B = B; p.C = C; p.Add = Add; p.S3 = S3;
    p.lda = lda; p.ldb = ldb; p.ldc = ldc; p.K3 = K3; p.alpha = alpha;
    p.bdiv = bdiv; p.sAo = sAo; p.sAi = sAi; p.sBo = sBo; p.sBi = sBi;
    p.sCo = sCo; p.sCi = sCi;
    p.tilesM = M / 128; p.tilesN = N / 128;
    p.total = bz * p.tilesM * p.tilesN;
    p.mode = mode; p.causal = causal;
    p.fused = 0;
    p.Az[0] = p.Az[1] = p.Az[2] = 0;
    p.Bz[0] = p.Bz[1] = p.Bz[2] = 0;
    p.S3z[0] = p.S3z[1] = p.S3z[2] = 0;
    p.modez[0] = p.modez[1] = p.modez[2] = 0;
    int grid = g_grid < p.total ? g_grid : p.total;
    mm_bf16_kernel<<<grid, 256, MM_SMEM>>>(p);
}

extern "C" void kernel_launch(void* const* d_in, const int* in_sizes, int n_in,
                              void* d_out, int out_size) {
    const float* x     = (const float*)d_in[0];
    const float* w_in  = (const float*)d_in[1];
    const float* wc1   = (const float*)d_in[6];
    const float* bc1   = (const float*)d_in[7];
    const float* wc2   = (const float*)d_in[8];
    const float* bc2   = (const float*)d_in[9];
    const float* wq    = (const float*)d_in[10];
    const float* wk    = (const float*)d_in[11];
    const float* wv    = (const float*)d_in[12];
    const float* wo    = (const float*)d_in[13];
    const float* w_nc  = (const float*)d_in[14];
    const float* w_ns  = (const float*)d_in[15];
    const float* w_fgv = (const float*)d_in[16];
    const float* w_np  = (const float*)d_in[17];
    const float* w_out = (const float*)d_in[18];
    float* out = (float*)d_out;

    int smc = 148;
    cudaDeviceGetAttribute(&smc, cudaDevAttrMultiProcessorCount, 0);
    g_grid = 2 * smc;

    cudaFuncSetAttribute(mm_bf16_kernel, cudaFuncAttributeMaxDynamicSharedMemorySize, MM_SMEM);

    float *xn, *xm, *hs, *coef, *sc, *slr, *gvb, *cw1;
    cudaGetSymbolAddress((void**)&xn,   g_xn);
    cudaGetSymbolAddress((void**)&xm,   g_xmean);
    cudaGetSymbolAddress((void**)&hs,   g_hs);
    cudaGetSymbolAddress((void**)&coef, g_coef);
    cudaGetSymbolAddress((void**)&sc,   g_sc);
    cudaGetSymbolAddress((void**)&slr,  g_slr);
    cudaGetSymbolAddress((void**)&gvb,  g_gv);
    cudaGetSymbolAddress((void**)&cw1,  g_cw1);

    __nv_bfloat16 *xn3, *kv3, *attn3, *fus3, *h23, *q3, *k3, *p3, *vt3;
    __nv_bfloat16 *wq3, *wk3, *wv3, *wo3, *wout3, *wfgvb3, *wt13, *cf3, *cw1t3, *tsc3;
    cudaGetSymbolAddress((void**)&xn3,    g3_xn);
    cudaGetSymbolAddress((void**)&kv3,    g3_kv);
    cudaGetSymbolAddress((void**)&attn3,  g3_attn);
    cudaGetSymbolAddress((void**)&fus3,   g3_fus);
    cudaGetSymbolAddress((void**)&h23,    g3_h2);
    cudaGetSymbolAddress((void**)&q3,     g3_q);
    cudaGetSymbolAddress((void**)&k3,     g3_k);
    cudaGetSymbolAddress((void**)&p3,     g3_p);
    cudaGetSymbolAddress((void**)&vt3,    g3_vt);
    cudaGetSymbolAddress((void**)&wq3,    g3_wq);
    cudaGetSymbolAddress((void**)&wk3,    g3_wk);
    cudaGetSymbolAddress((void**)&wv3,    g3_wv);
    cudaGetSymbolAddress((void**)&wo3,    g3_wo);
    cudaGetSymbolAddress((void**)&wout3,  g3_wout);
    cudaGetSymbolAddress((void**)&wfgvb3, g3_wfgvb);
    cudaGetSymbolAddress((void**)&wt13,   g3_wt1);
    cudaGetSymbolAddress((void**)&cf3,    g3_cf);
    cudaGetSymbolAddress((void**)&cw1t3,  g3_cw1t);
    cudaGetSymbolAddress((void**)&tsc3,   g3_tsc);

    dim3 tblk(32, 8);
    {
        T5Params tp;
        tp.W[0] = wq;    tp.Y[0] = wq3;
        tp.W[1] = wk;    tp.Y[1] = wk3;
        tp.W[2] = wv;    tp.Y[2] = wv3;
        tp.W[3] = wo;    tp.Y[3] = wo3;
        tp.W[4] = w_out; tp.Y[4] = wout3;
        transpose_split5_kernel<<<dim3(CD / 32, CD / 64, 5), tblk>>>(tp);
    }
    transpose_split_kernel<<<dim3((2 * CD) / 32, CD / 64), tblk>>>(
        w_fgv + (long long)CD * (2 * CD), wfgvb3, CD, 2 * CD);
    wt1_split_kernel<<<dim3((2 * CD) / 32, CD / 64), tblk>>>(w_fgv, wt13);

    rmsnorm_split_kernel<<<MT, 256>>>(x, w_in, xn, xn3, CD, 0);
    colmean_kernel<<<(CB * CD) / 256, 256>>>(xn, xm);
    mlp2_kernel<<<dim3(CDQ / 256, CB), 256>>>(xm, wc1, bc1, hs);
    coeff2_kernel<<<dim3(CNC / 256, CB), 256>>>(hs, wc2, bc2, coef);
    coeff3_kernel<<<dim3(8, 128), 256>>>(coef, w_nc, cf3);
    cheby3_kernel<<<MT, 256>>>(xn, coef, kv3, tsc3);

    // CW1 = coeff3 @ WT1 (batched over 8 heads)
    mm(cf3, wt13, cw1, 0, 0, 128, 2 * CD, 768, 768, 768, 2 * CD, 1.f,
       8, 1, (long long)128 * 768, 0, (long long)(2 * CD) * 768, 0,
       (long long)128 * (2 * CD), 0, 0, 0);
    cw1t_kernel<<<dim3((2 * CD) / 256, CB), 256>>>(cw1, cw1t3);

    // fused q/k/v projections: one persistent launch, per-z operands
    {
        MMParams p;
        p.A = xn3; p.B = wq3; p.C = 0; p.Add = 0; p.S3 = q3;
        p.lda = 3 * CD; p.ldb = 3 * CD; p.ldc = CD; p.K3 = 3 * CD; p.alpha = 1.f;
        p.bdiv = 1;
        p.sAo = 0; p.sAi = 0; p.sBo = 0; p.sBi = 0; p.sCo = 0; p.sCi = 0;
        p.tilesM = MT / 128; p.tilesN = CD / 128;
        p.total = 3 * p.tilesM * p.tilesN;
        p.mode = 1; p.causal = 0;
        p.fused = 1;
        p.Az[0] = xn3; p.Bz[0] = wq3; p.S3z[0] = q3;  p.modez[0] = 1;
        p.Az[1] = kv3; p.Bz[1] = wk3; p.S3z[1] = k3;  p.modez[1] = 2;
        p.Az[2] = kv3; p.Bz[2] = wv3; p.S3z[2] = vt3; p.modez[2] = 4;
        int grid = g_grid < p.total ? g_grid : p.total;
        mm_bf16_kernel<<<grid, 256, MM_SMEM>>>(p);
    }

    // scores = q @ k^T / sqrt(hd) with causal tile skip
    mm(q3, k3, sc, 0, 0, CS, CS, 384, 3 * CD, 3 * CD, CS, 0.08838834764831845f,
       CB * CAH, CAH,
       (long long)CS * 3 * CD, 384,
       (long long)CS * 3 * CD, 384,
       (long long)CAH * CS * CS, (long long)CS * CS, 0, 1);

    softmax_split_kernel<<<CB * CAH * CS, 256>>>(sc, p3);

    // attn = P @ V -> attn3 split epilogue
    mm(p3, vt3, 0, 0, attn3, CS, CAHD, 3 * CS, 3 * CS, 3 * CS, CD, 1.f,
       CB * CAH, CAH,
       (long long)CAH * CS * 3 * CS, (long long)CS * 3 * CS,
       (long long)CAH * CAHD * 3 * CS, (long long)CAHD * 3 * CS,
       0, 0, 3, 0);

    // slr = attn @ wo
    mm(attn3, wo3, slr, 0, 0, MT, CD, 3 * CD, 3 * CD, 3 * CD, CD, 1.f,
       1, 1, 0, 0, 0, 0, 0, 0, 0, 0);

    // h2 = split(rmsnorm(slr, w_ns))
    rmsnorm_split_kernel<<<MT, 256>>>(slr, w_ns, 0, h23, CD, 0);

    // gv = (rs*T) @ CW1^T  (low-rank h1 path)
    mm(tsc3, cw1t3, gvb, 0, 0, CS, 2 * CD, 96, 96, 96, 2 * CD, 1.f,
       CB, 1, (long long)CS * 96, 0, (long long)(2 * CD) * 96, 0,
       (long long)CS * (2 * CD), 0, 0, 0);
    // gv += h2 @ wfgv_bottom
    mm(h23, wfgvb3, gvb, gvb, 0, MT, 2 * CD, 3 * CD, 3 * CD, 3 * CD, 2 * CD, 1.f,
       1, 1, 0, 0, 0, 0, 0, 0, 0, 0);

    fuse_split_kernel<<<MT, 256>>>(gvb, w_np, fus3);
    // out = x + fused @ w_out
    mm(fus3, wout3, out, x, 0, MT, CD, 3 * CD, 3 * CD, 3 * CD, CD, 1.f,
       1, 1, 0, 0, 0, 0, 0, 0, 0, 0);
}